// round 10
// baseline (speedup 1.0000x reference)
#include <cuda_runtime.h>
#include <cuda_bf16.h>
#include <cstdint>

#define NG 8
#define NE 8192
#define NN 512
#define NP1 513
#define HH 32
#define PLANE (513*513)

#define MATB 2304        // one staged matrix tile: 16 rows x 144B (36 floats)
#define BUFB (2*MATB)    // one buffer: angle + dists
#define WBUF (2*BUFB)    // per-warp: 2 buffers
#define DYNSZ (8*WBUF)   // 73728 B dynamic smem

// ---------------------------------------------------------------------------
// helpers
// ---------------------------------------------------------------------------
__device__ __forceinline__ unsigned packbf(float lo, float hi) {
    __nv_bfloat162 t = __floats2bfloat162_rn(lo, hi);
    return *reinterpret_cast<unsigned*>(&t);
}

__device__ __forceinline__ void mma_bf16(float* c, const unsigned* a, uint2 b) {
    asm volatile(
        "mma.sync.aligned.m16n8k16.row.col.f32.bf16.bf16.f32 "
        "{%0,%1,%2,%3}, {%4,%5,%6,%7}, {%8,%9}, {%0,%1,%2,%3};\n"
        : "+f"(c[0]), "+f"(c[1]), "+f"(c[2]), "+f"(c[3])
        : "r"(a[0]), "r"(a[1]), "r"(a[2]), "r"(a[3]), "r"(b.x), "r"(b.y));
}

__device__ __forceinline__ void mma_tf32(float* c, const unsigned* a, uint2 b) {
    asm volatile(
        "mma.sync.aligned.m16n8k8.row.col.f32.tf32.tf32.f32 "
        "{%0,%1,%2,%3}, {%4,%5,%6,%7}, {%8,%9}, {%0,%1,%2,%3};\n"
        : "+f"(c[0]), "+f"(c[1]), "+f"(c[2]), "+f"(c[3])
        : "r"(a[0]), "r"(a[1]), "r"(a[2]), "r"(a[3]), "r"(b.x), "r"(b.y));
}

__device__ __forceinline__ void cp16(uint32_t saddr, const void* gsrc) {
    asm volatile("cp.async.cg.shared.global [%0], [%1], 16;" :: "r"(saddr), "l"(gsrc));
}
__device__ __forceinline__ void cp_commit() {
    asm volatile("cp.async.commit_group;" ::: "memory");
}
template <int N>
__device__ __forceinline__ void cp_wait() {
    asm volatile("cp.async.wait_group %0;" :: "n"(N) : "memory");
}

// ---------------------------------------------------------------------------
// Kernel A: interior fill  out[g,h,i,j] for i,j in [1,512]
// block = 256 threads (8 warps) per (g,i) row; per-warp double-buffered
// cp.async staging of raw fp32 inputs (contiguous 1792B tiles); layer-1 MLP
// via tf32 mma (A-frags = raw fp32 LDS, conflict-free 36-float row stride);
// layer-2 via bf16 mma on register-resident hidden. 2 CTAs/SM.
// ---------------------------------------------------------------------------
__global__ __launch_bounds__(256, 2) void interior_kernel(
    const float* __restrict__ attn_bias,
    const float* __restrict__ angle,
    const float* __restrict__ dists,
    const float* __restrict__ ang_w1, const float* __restrict__ ang_b1,
    const float* __restrict__ ang_w2, const float* __restrict__ ang_b2,
    const float* __restrict__ md_w1,  const float* __restrict__ md_b1,
    const float* __restrict__ md_w2,  const float* __restrict__ md_b2,
    float* __restrict__ out)
{
    __shared__ uint2  wf1[2][4][4][32];   // tf32 layer-1 B-frags [mat][ks][n][lane]
    __shared__ uint2  wf2[2][2][4][32];   // bf16 layer-2 B-frags [mat][ss][n][lane]
    __shared__ float2 bfr[3][4][32];      // bias pairs [mat][n][lane]
    extern __shared__ char dyn[];         // per-warp staging buffers

    const int tid  = threadIdx.x;
    const int lane = tid & 31;
    const int warp = tid >> 5;
    const int qid  = lane >> 2;   // 0..7
    const int tq   = lane & 3;    // 0..3

    // ---- build fragments (weights tiny; L2-resident) ----
    for (int e = tid; e < 1024; e += 256) {
        const int p = e >> 5, ln = e & 31;
        const int m = p >> 4, ks = (p >> 2) & 3, n = p & 3;
        const int q = ln >> 2, t4 = ln & 3;
        const int k0 = ks * 8 + t4;            // <= 27, always valid
        const int k1 = k0 + 4;                 // >= 28 only when ks==3
        const int c  = n * 8 + q;
        const float* w = m ? md_w1 : ang_w1;
        unsigned u0 = __float_as_uint(w[k0 * 32 + c]);
        unsigned u1 = (k1 < 28) ? __float_as_uint(w[k1 * 32 + c]) : 0u;
        wf1[m][ks][n][ln] = make_uint2(u0, u1);
    }
    for (int e = tid; e < 512; e += 256) {
        const int p = e >> 5, ln = e & 31;
        const int m = p >> 3, ss = (p >> 2) & 1, n = p & 3;
        const int q = ln >> 2, t4 = ln & 3;
        const int r0 = ss * 16 + t4 * 2;
        const int c  = n * 8 + q;
        const float* w = m ? md_w2 : ang_w2;
        wf2[m][ss][n][ln] = make_uint2(packbf(w[r0 * 32 + c],       w[(r0 + 1) * 32 + c]),
                                       packbf(w[(r0 + 8) * 32 + c], w[(r0 + 9) * 32 + c]));
    }
    for (int e = tid; e < 384; e += 256) {
        const int mat = e >> 7, rem = e & 127, n = rem >> 5, ln = rem & 31;
        const int i2 = n * 8 + (ln & 3) * 2;
        float lo, hi;
        if (mat == 0)      { lo = ang_b1[i2];              hi = ang_b1[i2 + 1]; }
        else if (mat == 1) { lo = md_b1[i2];               hi = md_b1[i2 + 1]; }
        else               { lo = ang_b2[i2] + md_b2[i2];  hi = ang_b2[i2 + 1] + md_b2[i2 + 1]; }
        bfr[mat][n][ln] = make_float2(lo, hi);
    }
    // zero pad cols 28..35 of every staged row (cp.async only writes cols 0..27)
    {
        char* wb = dyn + warp * WBUF;
#pragma unroll
        for (int e2 = 0; e2 < 2; e2++) {
            const int e = lane + e2 * 32;             // 0..63: [buf][mat][row]
            char* p = wb + (e >> 5) * BUFB + ((e >> 4) & 1) * MATB + (e & 15) * 144 + 112;
            *(float4*)p = make_float4(0.f, 0.f, 0.f, 0.f);
            *(float4*)(p + 16) = make_float4(0.f, 0.f, 0.f, 0.f);
        }
    }
    __syncthreads();

    const int bid = blockIdx.x;
    const int g = bid >> 9;           // / 512
    const int i = (bid & 511) + 1;    // out row 1..512
    const size_t rowp = (size_t)(g * NN + (i - 1)) * NN * 28;
    const char* angRow = (const char*)(angle + rowp);
    const char* dstRow = (const char*)(dists + rowp);
    const float* attnRow = attn_bias + ((size_t)g * NP1 + i) * NP1;
    float* outRow = out + (size_t)g * HH * PLANE + (size_t)i * NP1;

    // per-lane cp.async smem offsets (chunk c -> row*144 + (c%7)*16)
    int cpo[4];
#pragma unroll
    for (int k = 0; k < 4; k++) {
        const int c = lane + 32 * k;
        cpo[k] = (c / 7) * 144 + (c % 7) * 16;
    }
    const uint32_t sbase = (uint32_t)__cvta_generic_to_shared(dyn) + warp * WBUF;

    // issue one tile's loads (tile data is 1792B contiguous per matrix)
    #define ISSUE(j0v, b)                                                      \
        {                                                                      \
            const char* ga = angRow + (size_t)(j0v) * 112;                     \
            const char* gd = dstRow + (size_t)(j0v) * 112;                     \
            const uint32_t sa = sbase + (b) * BUFB;                            \
            const uint32_t sd = sa + MATB;                                     \
            _Pragma("unroll")                                                  \
            for (int k = 0; k < 3; k++) {                                      \
                cp16(sa + cpo[k], ga + (lane + 32 * k) * 16);                  \
                cp16(sd + cpo[k], gd + (lane + 32 * k) * 16);                  \
            }                                                                  \
            if (lane < 16) {                                                   \
                cp16(sa + cpo[3], ga + (lane + 96) * 16);                      \
                cp16(sd + cpo[3], gd + (lane + 96) * 16);                      \
            }                                                                  \
            cp_commit();                                                       \
        }

    ISSUE(warp * 16, 0);
    ISSUE((warp + 8) * 16, 1);

    float at0 = __ldg(attnRow + warp * 16 + 1 + qid);
    float at1 = __ldg(attnRow + warp * 16 + 9 + qid);

#pragma unroll
    for (int it = 0; it < 4; it++) {
        const int b  = it & 1;
        const int j0 = (warp + it * 8) * 16;

        if (it < 3) cp_wait<1>(); else cp_wait<0>();
        __syncwarp();

        const float* fa = (const float*)(dyn + warp * WBUF + b * BUFB);
        const float* fd = fa + MATB / 4;

        const float cat0 = at0, cat1 = at1;
        if (it < 3) {
            const int jn = j0 + 128;
            at0 = __ldg(attnRow + jn + 1 + qid);
            at1 = __ldg(attnRow + jn + 9 + qid);
        }

        float c2[4][4];
#pragma unroll
        for (int n = 0; n < 4; n++) {
            const float2 bb = bfr[2][n][lane];
            c2[n][0] = bb.x; c2[n][1] = bb.y; c2[n][2] = bb.x; c2[n][3] = bb.y;
        }

        float hh[4][4];
        unsigned A[4];
        const int a_r0 = qid * 36;
        const int a_r1 = (qid + 8) * 36;

        // ---- MLP(angle) layer 1 (tf32) ----
#pragma unroll
        for (int n = 0; n < 4; n++) {
            const float2 bb = bfr[0][n][lane];
            hh[n][0] = bb.x; hh[n][1] = bb.y; hh[n][2] = bb.x; hh[n][3] = bb.y;
        }
#pragma unroll
        for (int ks = 0; ks < 4; ks++) {
            const int kc = ks * 8 + tq;
            A[0] = __float_as_uint(fa[a_r0 + kc]);
            A[1] = __float_as_uint(fa[a_r1 + kc]);
            A[2] = __float_as_uint(fa[a_r0 + kc + 4]);
            A[3] = __float_as_uint(fa[a_r1 + kc + 4]);
#pragma unroll
            for (int n = 0; n < 4; n++) mma_tf32(hh[n], A, wf1[0][ks][n][lane]);
        }
        // relu -> layer 2 (bf16)
#pragma unroll
        for (int ss = 0; ss < 2; ss++) {
            A[0] = packbf(fmaxf(hh[2*ss][0], 0.f), fmaxf(hh[2*ss][1], 0.f));
            A[1] = packbf(fmaxf(hh[2*ss][2], 0.f), fmaxf(hh[2*ss][3], 0.f));
            A[2] = packbf(fmaxf(hh[2*ss+1][0], 0.f), fmaxf(hh[2*ss+1][1], 0.f));
            A[3] = packbf(fmaxf(hh[2*ss+1][2], 0.f), fmaxf(hh[2*ss+1][3], 0.f));
#pragma unroll
            for (int n = 0; n < 4; n++) mma_bf16(c2[n], A, wf2[0][ss][n][lane]);
        }

        // ---- MLP(dists) layer 1 (tf32) ----
#pragma unroll
        for (int n = 0; n < 4; n++) {
            const float2 bb = bfr[1][n][lane];
            hh[n][0] = bb.x; hh[n][1] = bb.y; hh[n][2] = bb.x; hh[n][3] = bb.y;
        }
#pragma unroll
        for (int ks = 0; ks < 4; ks++) {
            const int kc = ks * 8 + tq;
            A[0] = __float_as_uint(fd[a_r0 + kc]);
            A[1] = __float_as_uint(fd[a_r1 + kc]);
            A[2] = __float_as_uint(fd[a_r0 + kc + 4]);
            A[3] = __float_as_uint(fd[a_r1 + kc + 4]);
#pragma unroll
            for (int n = 0; n < 4; n++) mma_tf32(hh[n], A, wf1[1][ks][n][lane]);
        }

        // staging buffer fully consumed -> refill for tile it+2
        __syncwarp();
        if (it < 2) ISSUE(j0 + 256, b);

        // relu -> layer 2 (bf16)
#pragma unroll
        for (int ss = 0; ss < 2; ss++) {
            A[0] = packbf(fmaxf(hh[2*ss][0], 0.f), fmaxf(hh[2*ss][1], 0.f));
            A[1] = packbf(fmaxf(hh[2*ss][2], 0.f), fmaxf(hh[2*ss][3], 0.f));
            A[2] = packbf(fmaxf(hh[2*ss+1][0], 0.f), fmaxf(hh[2*ss+1][1], 0.f));
            A[3] = packbf(fmaxf(hh[2*ss+1][2], 0.f), fmaxf(hh[2*ss+1][3], 0.f));
#pragma unroll
            for (int n = 0; n < 4; n++) mma_bf16(c2[n], A, wf2[1][ss][n][lane]);
        }

        // ---- add attn_bias base, store ----
#pragma unroll
        for (int n = 0; n < 4; n++) {
            float* o = outRow + (size_t)(n * 8 + tq * 2) * PLANE;
            o[j0 + 1 + qid]         = c2[n][0] + cat0;
            o[PLANE + j0 + 1 + qid] = c2[n][1] + cat0;
            o[j0 + 9 + qid]         = c2[n][2] + cat1;
            o[PLANE + j0 + 9 + qid] = c2[n][3] + cat1;
        }
    }
    #undef ISSUE
}

// ---------------------------------------------------------------------------
// Kernel B: border fill (row 0 and column 0): attn + virt
// ---------------------------------------------------------------------------
__global__ __launch_bounds__(256) void border_kernel(
    const float* __restrict__ attn_bias,
    const float* __restrict__ virt,
    float* __restrict__ out)
{
    const int idx = blockIdx.x * 256 + threadIdx.x;
    const int total = NG * HH * 1025;
    if (idx >= total) return;
    const int pos = idx % 1025;
    const int gh  = idx / 1025;
    const int h = gh & 31;
    const int g = gh >> 5;
    const float v = virt[h];
    float* ob = out + ((size_t)(g * HH + h)) * PLANE;
    const float* ab = attn_bias + (size_t)g * PLANE;
    if (pos < NP1) {
        ob[pos] = ab[pos] + v;                        // row 0, all j
    } else {
        const int i = pos - 512;                      // 1..512
        ob[(size_t)i * NP1] = ab[(size_t)i * NP1] + v; // col 0
    }
}

// ---------------------------------------------------------------------------
// Kernel C: edge scatter-add. One warp per edge, lane = head h.
// edge_mask is a jax bool materialized as int32 by the harness.
// ---------------------------------------------------------------------------
__global__ __launch_bounds__(256) void edge_kernel(
    const float* __restrict__ edge_feat,
    const int*   __restrict__ edge_index,
    const int*   __restrict__ edge_mask,
    const int*   __restrict__ num_ligand_atoms,
    const float* __restrict__ struct_emb,
    const float* __restrict__ plip_lig,
    const float* __restrict__ plip_prot,
    const float* __restrict__ plip_inter,
    const float* __restrict__ dist_w1, const float* __restrict__ dist_b1,
    const float* __restrict__ dist_w2, const float* __restrict__ dist_b2,
    float* __restrict__ out)
{
    __shared__ float s_w2[1024];
    __shared__ float s_w1[32], s_b1[32], s_b2[32];
    const int tid = threadIdx.x;
    for (int idx = tid; idx < 1024; idx += 256) s_w2[idx] = dist_w2[idx];
    if (tid < 32) {
        s_w1[tid] = dist_w1[tid];
        s_b1[tid] = dist_b1[tid];
        s_b2[tid] = dist_b2[tid];
    }
    __syncthreads();

    const int warp = tid >> 5;
    const int lane = tid & 31;
    const int eid = blockIdx.x * 8 + warp;     // 0 .. G*E-1 (grid exact)
    if (eid >= NG * NE) return;
    if (edge_mask[eid] == 0) return;           // masked edges contribute 0

    const int g = eid >> 13;                   // / 8192
    const int e = eid & (NE - 1);

    const float4 ef = reinterpret_cast<const float4*>(edge_feat)[eid];
    const int t0 = (int)ef.x;
    const int t1 = (int)ef.y;
    const int t2 = (int)ef.z;
    const float d = ef.w;

    const int src = edge_index[(size_t)g * 2 * NE + e];
    const int tgt = edge_index[(size_t)g * 2 * NE + NE + e];
    int nl = num_ligand_atoms[g];
    nl = nl > 1 ? nl : 1;
    const bool sl = (src > 0) && (src < nl);
    const bool tl = (tgt > 0) && (tgt < nl);

    // distance MLP: scalar -> 32 -> 32 (lane = output h)
    const float hid = fmaxf(fmaf(d, s_w1[lane], s_b1[lane]), 0.f);
    float y = s_b2[lane];
#pragma unroll
    for (int m = 0; m < 32; m++)
        y = fmaf(__shfl_sync(0xffffffffu, hid, m), s_w2[m * 32 + lane], y);

    float sel = 0.f;
    if (t0 <= 1) {
        int si = t0 * 4 + t1 * 2 + t2;
        si = si < 0 ? 0 : (si > 19 ? 19 : si);
        sel = struct_emb[si * 32 + lane];
    } else if (t0 == 5) {
        int pi = t1 < 0 ? 0 : (t1 > 14 ? 14 : t1);
        const float* tab = (sl && tl) ? plip_lig : ((!sl && !tl) ? plip_prot : plip_inter);
        sel = tab[pi * 32 + lane];
    }

    atomicAdd(out + (((size_t)(g * HH + lane)) * NP1 + (src + 1)) * NP1 + (tgt + 1), y + sel);
}

// ---------------------------------------------------------------------------
extern "C" void kernel_launch(void* const* d_in, const int* in_sizes, int n_in,
                              void* d_out, int out_size) {
    const float* edge_feat  = (const float*)d_in[0];
    const int*   edge_index = (const int*)d_in[1];
    const int*   edge_mask  = (const int*)d_in[2];
    const int*   num_lig    = (const int*)d_in[3];
    const float* attn_bias  = (const float*)d_in[4];
    const float* angle      = (const float*)d_in[5];
    const float* dists      = (const float*)d_in[6];
    // d_in[7] node_feat unused (shape only in reference)
    const float* struct_emb = (const float*)d_in[8];
    const float* plip_lig   = (const float*)d_in[9];
    const float* plip_prot  = (const float*)d_in[10];
    const float* plip_inter = (const float*)d_in[11];
    const float* dist_w1 = (const float*)d_in[12];
    const float* dist_b1 = (const float*)d_in[13];
    const float* dist_w2 = (const float*)d_in[14];
    const float* dist_b2 = (const float*)d_in[15];
    const float* ang_w1  = (const float*)d_in[16];
    const float* ang_b1  = (const float*)d_in[17];
    const float* ang_w2  = (const float*)d_in[18];
    const float* ang_b2  = (const float*)d_in[19];
    const float* md_w1   = (const float*)d_in[20];
    const float* md_b1   = (const float*)d_in[21];
    const float* md_w2   = (const float*)d_in[22];
    const float* md_b2   = (const float*)d_in[23];
    const float* virt    = (const float*)d_in[24];
    float* out = (float*)d_out;

    cudaFuncSetAttribute(interior_kernel,
                         cudaFuncAttributeMaxDynamicSharedMemorySize, DYNSZ);

    // interior + border overwrite the whole output (disjoint regions),
    // then edge kernel atomically adds on top (stream-ordered).
    interior_kernel<<<NG * NN, 256, DYNSZ>>>(attn_bias, angle, dists,
                                      ang_w1, ang_b1, ang_w2, ang_b2,
                                      md_w1, md_b1, md_w2, md_b2, out);
    border_kernel<<<(NG * HH * 1025 + 255) / 256, 256>>>(attn_bias, virt, out);
    edge_kernel<<<NG * NE / 8, 256>>>(edge_feat, edge_index, edge_mask, num_lig,
                                      struct_emb, plip_lig, plip_prot, plip_inter,
                                      dist_w1, dist_b1, dist_w2, dist_b2, out);
}

// round 11
// speedup vs baseline: 1.0830x; 1.0830x over previous
#include <cuda_runtime.h>
#include <cuda_bf16.h>
#include <cstdint>

#define NG 8
#define NE 8192
#define NN 512
#define NP1 513
#define HH 32
#define PLANE (513*513)
#define CAP 96          // per-(g,row) edge bucket capacity (max expected ~38)

// ---------------------------------------------------------------------------
// scratch (static __device__ arrays: allowed; no dynamic allocation)
// ---------------------------------------------------------------------------
__device__ float g_vals[NG * NE * HH];          // per-edge 32-head vector (8.4MB)
__device__ int   g_bucket[NG * NP1 * CAP];      // packed (e | col<<13)
__device__ int   g_cnt[NG * NP1];               // bucket counts

// ---------------------------------------------------------------------------
// helpers
// ---------------------------------------------------------------------------
__device__ __forceinline__ unsigned packbf(float lo, float hi) {
    __nv_bfloat162 t = __floats2bfloat162_rn(lo, hi);
    return *reinterpret_cast<unsigned*>(&t);
}
__device__ __forceinline__ unsigned packbf2(float2 v) { return packbf(v.x, v.y); }

__device__ __forceinline__ void mma_bf16(float* c, const unsigned* a, uint2 b) {
    asm volatile(
        "mma.sync.aligned.m16n8k16.row.col.f32.bf16.bf16.f32 "
        "{%0,%1,%2,%3}, {%4,%5,%6,%7}, {%8,%9}, {%0,%1,%2,%3};\n"
        : "+f"(c[0]), "+f"(c[1]), "+f"(c[2]), "+f"(c[3])
        : "r"(a[0]), "r"(a[1]), "r"(a[2]), "r"(a[3]), "r"(b.x), "r"(b.y));
}

__device__ __forceinline__ void ldm4(unsigned* r, uint32_t addr) {
    asm volatile("ldmatrix.sync.aligned.m8n8.x4.shared.b16 {%0,%1,%2,%3}, [%4];"
                 : "=r"(r[0]), "=r"(r[1]), "=r"(r[2]), "=r"(r[3]) : "r"(addr));
}

// ---------------------------------------------------------------------------
// init: zero bucket counters (every launch -> deterministic)
// ---------------------------------------------------------------------------
__global__ void init_kernel() {
    for (int i = blockIdx.x * 256 + threadIdx.x; i < NG * NP1; i += gridDim.x * 256)
        g_cnt[i] = 0;
}

// ---------------------------------------------------------------------------
// efill: per-edge MLP + embedding -> g_vals; push packed entry into row bucket.
// One warp per edge, lane = head h. edge_mask is int32 (jax bool).
// ---------------------------------------------------------------------------
__global__ __launch_bounds__(256) void efill_kernel(
    const float* __restrict__ edge_feat,
    const int*   __restrict__ edge_index,
    const int*   __restrict__ edge_mask,
    const int*   __restrict__ num_ligand_atoms,
    const float* __restrict__ struct_emb,
    const float* __restrict__ plip_lig,
    const float* __restrict__ plip_prot,
    const float* __restrict__ plip_inter,
    const float* __restrict__ dist_w1, const float* __restrict__ dist_b1,
    const float* __restrict__ dist_w2, const float* __restrict__ dist_b2)
{
    __shared__ float s_w2[1024];
    __shared__ float s_w1[32], s_b1[32], s_b2[32];
    const int tid = threadIdx.x;
    for (int idx = tid; idx < 1024; idx += 256) s_w2[idx] = dist_w2[idx];
    if (tid < 32) {
        s_w1[tid] = dist_w1[tid];
        s_b1[tid] = dist_b1[tid];
        s_b2[tid] = dist_b2[tid];
    }
    __syncthreads();

    const int warp = tid >> 5;
    const int lane = tid & 31;
    const int eid = blockIdx.x * 8 + warp;
    if (eid >= NG * NE) return;
    if (edge_mask[eid] == 0) return;

    const int g = eid >> 13;
    const int e = eid & (NE - 1);

    const float4 ef = reinterpret_cast<const float4*>(edge_feat)[eid];
    const int t0 = (int)ef.x;
    const int t1 = (int)ef.y;
    const int t2 = (int)ef.z;
    const float d = ef.w;

    const int src = edge_index[(size_t)g * 2 * NE + e];
    const int tgt = edge_index[(size_t)g * 2 * NE + NE + e];
    int nl = num_ligand_atoms[g];
    nl = nl > 1 ? nl : 1;
    const bool sl = (src > 0) && (src < nl);
    const bool tl = (tgt > 0) && (tgt < nl);

    const float hid = fmaxf(fmaf(d, s_w1[lane], s_b1[lane]), 0.f);
    float y = s_b2[lane];
#pragma unroll
    for (int m = 0; m < 32; m++)
        y = fmaf(__shfl_sync(0xffffffffu, hid, m), s_w2[m * 32 + lane], y);

    float sel = 0.f;
    if (t0 <= 1) {
        int si = t0 * 4 + t1 * 2 + t2;
        si = si < 0 ? 0 : (si > 19 ? 19 : si);
        sel = struct_emb[si * 32 + lane];
    } else if (t0 == 5) {
        int pi = t1 < 0 ? 0 : (t1 > 14 ? 14 : t1);
        const float* tab = (sl && tl) ? plip_lig : ((!sl && !tl) ? plip_prot : plip_inter);
        sel = tab[pi * 32 + lane];
    }

    g_vals[(size_t)eid * HH + lane] = y + sel;       // coalesced 128B

    if (lane == 0) {
        const int row = src + 1;                      // 1..512
        const int slot = atomicAdd(&g_cnt[g * NP1 + row], 1);
        if (slot < CAP)
            g_bucket[(g * NP1 + row) * CAP + slot] = e | ((tgt + 1) << 13);
    }
}

// ---------------------------------------------------------------------------
// Kernel A: interior fill  out[g,h,i,j] for i,j in [1,512]  (R8 structure)
// + fused edge contributions from this row's bucket.
// ---------------------------------------------------------------------------
__global__ __launch_bounds__(256, 2) void interior_kernel(
    const float* __restrict__ attn_bias,
    const float* __restrict__ angle,
    const float* __restrict__ dists,
    const float* __restrict__ ang_w1, const float* __restrict__ ang_b1,
    const float* __restrict__ ang_w2, const float* __restrict__ ang_b2,
    const float* __restrict__ md_w1,  const float* __restrict__ md_b1,
    const float* __restrict__ md_w2,  const float* __restrict__ md_b2,
    float* __restrict__ out)
{
    __shared__ uint2  wfrag[32][32];                       // [m*8+s*4+n][lane]
    __shared__ float2 bfr[3][4][32];                       // [mat][n][lane]
    __shared__ __align__(128) unsigned char mbuf[8][2560]; // per-warp ldmatrix buf

    const int tid = threadIdx.x;

    for (int e = tid; e < 1024; e += 256) {
        const int p = e >> 5, ln = e & 31;
        const int m = p >> 3, s = (p >> 2) & 1, n = p & 3;
        const int q = ln >> 2, tq4 = ln & 3;
        const int r0 = s * 16 + tq4 * 2;
        const int c  = n * 8 + q;
        const float* w = (m == 0) ? ang_w1 : (m == 1) ? md_w1 : (m == 2) ? ang_w2 : md_w2;
        const bool pad = (m < 2);
        float v00 = (pad && r0     >= 28) ? 0.f : w[(r0)     * 32 + c];
        float v01 = (pad && r0 + 1 >= 28) ? 0.f : w[(r0 + 1) * 32 + c];
        float v10 = (pad && r0 + 8 >= 28) ? 0.f : w[(r0 + 8) * 32 + c];
        float v11 = (pad && r0 + 9 >= 28) ? 0.f : w[(r0 + 9) * 32 + c];
        wfrag[p][ln] = make_uint2(packbf(v00, v01), packbf(v10, v11));
    }
    for (int e = tid; e < 384; e += 256) {
        const int mat = e >> 7, rem = e & 127, n = rem >> 5, ln = rem & 31;
        const int i2 = n * 8 + (ln & 3) * 2;
        float lo, hi;
        if (mat == 0)      { lo = ang_b1[i2];              hi = ang_b1[i2 + 1]; }
        else if (mat == 1) { lo = md_b1[i2];               hi = md_b1[i2 + 1]; }
        else               { lo = ang_b2[i2] + md_b2[i2];  hi = ang_b2[i2 + 1] + md_b2[i2 + 1]; }
        bfr[mat][n][ln] = make_float2(lo, hi);
    }
    *(float2*)(mbuf[tid >> 5] + (tid & 31) * 80 + 56) = make_float2(0.f, 0.f);
    __syncthreads();

    const int lane = tid & 31;
    const int warp = tid >> 5;
    const int qid  = lane >> 2;
    const int tq   = lane & 3;

    const int bid = blockIdx.x;
    const int g = bid >> 9;
    const int i = (bid & 511) + 1;
    const size_t rowp = (size_t)(g * NN + (i - 1)) * NN * 28;
    const float* angRow  = angle + rowp;
    const float* dstRow  = dists + rowp;
    const float* attnRow = attn_bias + ((size_t)g * NP1 + i) * NP1;
    float* outRow = out + (size_t)g * HH * PLANE + (size_t)i * NP1;

    // ---- edge bucket for this row (warp-resident) ----
    const int ne = min(g_cnt[g * NP1 + i], CAP);
    const int bbase = (g * NP1 + i) * CAP;
    int eb0 = (lane      < ne) ? g_bucket[bbase + lane]      : -1;
    int eb1 = (lane + 32 < ne) ? g_bucket[bbase + lane + 32] : -1;
    int eb2 = (lane + 64 < ne) ? g_bucket[bbase + lane + 64] : -1;

    const uint32_t abase = (uint32_t)__cvta_generic_to_shared(mbuf[warp]);
    const uint32_t dbase = abase + 1280;
    const uint32_t lm_off = (uint32_t)((lane & 15) * 80 + ((lane >> 4) << 4));

    float2 ra[7], rd[7];
    float at0, at1;
    {
        const float2* a2 = (const float2*)angRow + (size_t)(warp * 16) * 14;
        const float2* d2 = (const float2*)dstRow + (size_t)(warp * 16) * 14;
#pragma unroll
        for (int k = 0; k < 7; k++) {
            ra[k] = __ldcs(a2 + lane + 32 * k);
            rd[k] = __ldcs(d2 + lane + 32 * k);
        }
        at0 = __ldg(attnRow + warp * 16 + 1 + qid);
        at1 = __ldg(attnRow + warp * 16 + 9 + qid);
    }

#pragma unroll
    for (int it = 0; it < 4; it++) {
        const int t  = warp + it * 8;
        const int j0 = t * 16;

        __syncwarp();
#pragma unroll
        for (int k = 0; k < 7; k++) {
            const int f   = lane + 32 * k;
            const int row = f / 14;
            const int c   = f - row * 14;
            const int off = row * 80 + c * 4;
            *(unsigned*)(mbuf[warp] + off)        = packbf2(ra[k]);
            *(unsigned*)(mbuf[warp] + 1280 + off) = packbf2(rd[k]);
        }
        __syncwarp();

        unsigned Aa0[4], Aa1[4], Ad0[4], Ad1[4];
        ldm4(Aa0, abase + lm_off);
        ldm4(Aa1, abase + lm_off + 32);
        ldm4(Ad0, dbase + lm_off);
        ldm4(Ad1, dbase + lm_off + 32);

        const float cat0 = at0, cat1 = at1;

        if (it < 3) {
            const int jn = (t + 8) * 16;
            const float2* a2 = (const float2*)angRow + (size_t)jn * 14;
            const float2* d2 = (const float2*)dstRow + (size_t)jn * 14;
#pragma unroll
            for (int k = 0; k < 7; k++) {
                ra[k] = __ldcs(a2 + lane + 32 * k);
                rd[k] = __ldcs(d2 + lane + 32 * k);
            }
            at0 = __ldg(attnRow + jn + 1 + qid);
            at1 = __ldg(attnRow + jn + 9 + qid);
        }

        float c2[4][4];
#pragma unroll
        for (int n = 0; n < 4; n++) {
            const float2 bb = bfr[2][n][lane];
            c2[n][0] = bb.x; c2[n][1] = bb.y; c2[n][2] = bb.x; c2[n][3] = bb.y;
        }

        float hh[4][4];
        unsigned A[4];

        // MLP(angle) layer 1
#pragma unroll
        for (int n = 0; n < 4; n++) {
            const float2 bb = bfr[0][n][lane];
            hh[n][0] = bb.x; hh[n][1] = bb.y; hh[n][2] = bb.x; hh[n][3] = bb.y;
        }
#pragma unroll
        for (int n = 0; n < 4; n++) mma_bf16(hh[n], Aa0, wfrag[0 + n][lane]);
#pragma unroll
        for (int n = 0; n < 4; n++) mma_bf16(hh[n], Aa1, wfrag[4 + n][lane]);
        // relu -> layer 2 (ang_w2)
#pragma unroll
        for (int ss = 0; ss < 2; ss++) {
            A[0] = packbf(fmaxf(hh[2*ss][0], 0.f), fmaxf(hh[2*ss][1], 0.f));
            A[1] = packbf(fmaxf(hh[2*ss][2], 0.f), fmaxf(hh[2*ss][3], 0.f));
            A[2] = packbf(fmaxf(hh[2*ss+1][0], 0.f), fmaxf(hh[2*ss+1][1], 0.f));
            A[3] = packbf(fmaxf(hh[2*ss+1][2], 0.f), fmaxf(hh[2*ss+1][3], 0.f));
#pragma unroll
            for (int n = 0; n < 4; n++) mma_bf16(c2[n], A, wfrag[16 + ss * 4 + n][lane]);
        }

        // MLP(dists) layer 1
#pragma unroll
        for (int n = 0; n < 4; n++) {
            const float2 bb = bfr[1][n][lane];
            hh[n][0] = bb.x; hh[n][1] = bb.y; hh[n][2] = bb.x; hh[n][3] = bb.y;
        }
#pragma unroll
        for (int n = 0; n < 4; n++) mma_bf16(hh[n], Ad0, wfrag[8 + n][lane]);
#pragma unroll
        for (int n = 0; n < 4; n++) mma_bf16(hh[n], Ad1, wfrag[12 + n][lane]);
        // relu -> layer 2 (md_w2)
#pragma unroll
        for (int ss = 0; ss < 2; ss++) {
            A[0] = packbf(fmaxf(hh[2*ss][0], 0.f), fmaxf(hh[2*ss][1], 0.f));
            A[1] = packbf(fmaxf(hh[2*ss][2], 0.f), fmaxf(hh[2*ss][3], 0.f));
            A[2] = packbf(fmaxf(hh[2*ss+1][0], 0.f), fmaxf(hh[2*ss+1][1], 0.f));
            A[3] = packbf(fmaxf(hh[2*ss+1][2], 0.f), fmaxf(hh[2*ss+1][3], 0.f));
#pragma unroll
            for (int n = 0; n < 4; n++) mma_bf16(c2[n], A, wfrag[24 + ss * 4 + n][lane]);
        }

        // ---- fused edge contributions for this 16-j window ----
        if (ne) {
#pragma unroll
            for (int half = 0; half < 3; half++) {
                const int ereg = (half == 0) ? eb0 : (half == 1) ? eb1 : eb2;
                unsigned m = __ballot_sync(0xffffffffu,
                    ereg >= 0 && (unsigned)((ereg >> 13) - 1 - j0) < 16u);
                while (m) {
                    const int k = __ffs(m) - 1;
                    m &= m - 1;
                    const int ent = __shfl_sync(0xffffffffu, ereg, k);
                    const int rel = (ent >> 13) - 1 - j0;     // 0..15
                    const int e   = ent & (NE - 1);
                    const float2* vp = (const float2*)(g_vals + (size_t)(g * NE + e) * HH);
                    if (rel < 8) {
                        if (qid == rel) {
#pragma unroll
                            for (int n = 0; n < 4; n++) {
                                const float2 v = vp[n * 4 + tq];
                                c2[n][0] += v.x; c2[n][1] += v.y;
                            }
                        }
                    } else {
                        if (qid == rel - 8) {
#pragma unroll
                            for (int n = 0; n < 4; n++) {
                                const float2 v = vp[n * 4 + tq];
                                c2[n][2] += v.x; c2[n][3] += v.y;
                            }
                        }
                    }
                }
            }
        }

        // ---- add attn_bias base, store ----
#pragma unroll
        for (int n = 0; n < 4; n++) {
            float* o = outRow + (size_t)(n * 8 + tq * 2) * PLANE;
            o[j0 + 1 + qid]         = c2[n][0] + cat0;
            o[PLANE + j0 + 1 + qid] = c2[n][1] + cat0;
            o[j0 + 9 + qid]         = c2[n][2] + cat1;
            o[PLANE + j0 + 9 + qid] = c2[n][3] + cat1;
        }
    }
}

// ---------------------------------------------------------------------------
// Kernel B: border fill (row 0 and column 0): attn + virt
// ---------------------------------------------------------------------------
__global__ __launch_bounds__(256) void border_kernel(
    const float* __restrict__ attn_bias,
    const float* __restrict__ virt,
    float* __restrict__ out)
{
    const int idx = blockIdx.x * 256 + threadIdx.x;
    const int total = NG * HH * 1025;
    if (idx >= total) return;
    const int pos = idx % 1025;
    const int gh  = idx / 1025;
    const int h = gh & 31;
    const int g = gh >> 5;
    const float v = virt[h];
    float* ob = out + ((size_t)(g * HH + h)) * PLANE;
    const float* ab = attn_bias + (size_t)g * PLANE;
    if (pos < NP1) {
        ob[pos] = ab[pos] + v;                         // row 0
    } else {
        const int i = pos - 512;                       // 1..512
        ob[(size_t)i * NP1] = ab[(size_t)i * NP1] + v; // col 0
    }
}

// ---------------------------------------------------------------------------
extern "C" void kernel_launch(void* const* d_in, const int* in_sizes, int n_in,
                              void* d_out, int out_size) {
    const float* edge_feat  = (const float*)d_in[0];
    const int*   edge_index = (const int*)d_in[1];
    const int*   edge_mask  = (const int*)d_in[2];
    const int*   num_lig    = (const int*)d_in[3];
    const float* attn_bias  = (const float*)d_in[4];
    const float* angle      = (const float*)d_in[5];
    const float* dists      = (const float*)d_in[6];
    // d_in[7] node_feat unused
    const float* struct_emb = (const float*)d_in[8];
    const float* plip_lig   = (const float*)d_in[9];
    const float* plip_prot  = (const float*)d_in[10];
    const float* plip_inter = (const float*)d_in[11];
    const float* dist_w1 = (const float*)d_in[12];
    const float* dist_b1 = (const float*)d_in[13];
    const float* dist_w2 = (const float*)d_in[14];
    const float* dist_b2 = (const float*)d_in[15];
    const float* ang_w1  = (const float*)d_in[16];
    const float* ang_b1  = (const float*)d_in[17];
    const float* ang_w2  = (const float*)d_in[18];
    const float* ang_b2  = (const float*)d_in[19];
    const float* md_w1   = (const float*)d_in[20];
    const float* md_b1   = (const float*)d_in[21];
    const float* md_w2   = (const float*)d_in[22];
    const float* md_b2   = (const float*)d_in[23];
    const float* virt    = (const float*)d_in[24];
    float* out = (float*)d_out;

    // init buckets -> edge vals+buckets -> interior (consumes) -> border
    init_kernel<<<17, 256>>>();
    efill_kernel<<<NG * NE / 8, 256>>>(edge_feat, edge_index, edge_mask, num_lig,
                                       struct_emb, plip_lig, plip_prot, plip_inter,
                                       dist_w1, dist_b1, dist_w2, dist_b2);
    interior_kernel<<<NG * NN, 256>>>(attn_bias, angle, dists,
                                      ang_w1, ang_b1, ang_w2, ang_b2,
                                      md_w1, md_b1, md_w2, md_b2, out);
    border_kernel<<<(NG * HH * 1025 + 255) / 256, 256>>>(attn_bias, virt, out);
}

// round 12
// speedup vs baseline: 1.2116x; 1.1187x over previous
#include <cuda_runtime.h>
#include <cuda_bf16.h>
#include <cstdint>

#define NG 8
#define NE 8192
#define NN 512
#define NP1 513
#define HH 32
#define PLANE (513*513)
#define CAP 96          // per-(g,row) edge bucket capacity (max expected ~38)

// ---------------------------------------------------------------------------
// scratch (static __device__ arrays; zero-initialized at module load).
// g_cnt is self-cleaning: interior zeros each entry after consuming it, so
// every execution (correctness run, each graph replay) starts from zeros.
// ---------------------------------------------------------------------------
__device__ float g_vals[NG * NE * HH];          // per-edge 32-head vector (8.4MB)
__device__ int   g_bucket[NG * NP1 * CAP];      // packed (e | col<<13)
__device__ int   g_cnt[NG * NP1];               // bucket counts

// ---------------------------------------------------------------------------
// helpers
// ---------------------------------------------------------------------------
__device__ __forceinline__ unsigned packbf(float lo, float hi) {
    __nv_bfloat162 t = __floats2bfloat162_rn(lo, hi);
    return *reinterpret_cast<unsigned*>(&t);
}
__device__ __forceinline__ unsigned packbf2(float2 v) { return packbf(v.x, v.y); }

__device__ __forceinline__ void mma_bf16(float* c, const unsigned* a, uint2 b) {
    asm volatile(
        "mma.sync.aligned.m16n8k16.row.col.f32.bf16.bf16.f32 "
        "{%0,%1,%2,%3}, {%4,%5,%6,%7}, {%8,%9}, {%0,%1,%2,%3};\n"
        : "+f"(c[0]), "+f"(c[1]), "+f"(c[2]), "+f"(c[3])
        : "r"(a[0]), "r"(a[1]), "r"(a[2]), "r"(a[3]), "r"(b.x), "r"(b.y));
}

__device__ __forceinline__ void ldm4(unsigned* r, uint32_t addr) {
    asm volatile("ldmatrix.sync.aligned.m8n8.x4.shared.b16 {%0,%1,%2,%3}, [%4];"
                 : "=r"(r[0]), "=r"(r[1]), "=r"(r[2]), "=r"(r[3]) : "r"(addr));
}

// ---------------------------------------------------------------------------
// efill: per-edge MLP + embedding -> g_vals; push packed entry into row bucket.
// One warp handles 8 edges (amortizes the 4KB weight smem load); lane = head.
// edge_mask is int32 (jax bool).
// ---------------------------------------------------------------------------
__global__ __launch_bounds__(256) void efill_kernel(
    const float* __restrict__ edge_feat,
    const int*   __restrict__ edge_index,
    const int*   __restrict__ edge_mask,
    const int*   __restrict__ num_ligand_atoms,
    const float* __restrict__ struct_emb,
    const float* __restrict__ plip_lig,
    const float* __restrict__ plip_prot,
    const float* __restrict__ plip_inter,
    const float* __restrict__ dist_w1, const float* __restrict__ dist_b1,
    const float* __restrict__ dist_w2, const float* __restrict__ dist_b2)
{
    __shared__ float s_w2[1024];
    __shared__ float s_w1[32], s_b1[32], s_b2[32];
    const int tid = threadIdx.x;
    for (int idx = tid; idx < 1024; idx += 256) s_w2[idx] = dist_w2[idx];
    if (tid < 32) {
        s_w1[tid] = dist_w1[tid];
        s_b1[tid] = dist_b1[tid];
        s_b2[tid] = dist_b2[tid];
    }
    __syncthreads();

    const int warp = tid >> 5;
    const int lane = tid & 31;
    const int ebase = blockIdx.x * 64 + warp * 8;   // grid exact: NG*NE/64 blocks

#pragma unroll 1
    for (int s = 0; s < 8; s++) {
        const int eid = ebase + s;
        if (edge_mask[eid] == 0) continue;           // uniform per warp

        const int g = eid >> 13;
        const int e = eid & (NE - 1);

        const float4 ef = reinterpret_cast<const float4*>(edge_feat)[eid];
        const int t0 = (int)ef.x;
        const int t1 = (int)ef.y;
        const int t2 = (int)ef.z;
        const float d = ef.w;

        const int src = edge_index[(size_t)g * 2 * NE + e];
        const int tgt = edge_index[(size_t)g * 2 * NE + NE + e];
        int nl = num_ligand_atoms[g];
        nl = nl > 1 ? nl : 1;
        const bool sl = (src > 0) && (src < nl);
        const bool tl = (tgt > 0) && (tgt < nl);

        const float hid = fmaxf(fmaf(d, s_w1[lane], s_b1[lane]), 0.f);
        float y = s_b2[lane];
#pragma unroll
        for (int m = 0; m < 32; m++)
            y = fmaf(__shfl_sync(0xffffffffu, hid, m), s_w2[m * 32 + lane], y);

        float sel = 0.f;
        if (t0 <= 1) {
            int si = t0 * 4 + t1 * 2 + t2;
            si = si < 0 ? 0 : (si > 19 ? 19 : si);
            sel = struct_emb[si * 32 + lane];
        } else if (t0 == 5) {
            int pi = t1 < 0 ? 0 : (t1 > 14 ? 14 : t1);
            const float* tab = (sl && tl) ? plip_lig : ((!sl && !tl) ? plip_prot : plip_inter);
            sel = tab[pi * 32 + lane];
        }

        g_vals[(size_t)eid * HH + lane] = y + sel;   // coalesced 128B

        if (lane == 0) {
            const int row = src + 1;                  // 1..512
            const int slot = atomicAdd(&g_cnt[g * NP1 + row], 1);
            if (slot < CAP)
                g_bucket[(g * NP1 + row) * CAP + slot] = e | ((tgt + 1) << 13);
        }
    }
}

// ---------------------------------------------------------------------------
// Kernel A: interior fill  out[g,h,i,j] for i,j in [1,512]  (R8 structure)
// + fused edge contributions + col-0 (attn + virt) + self-cleaning g_cnt.
// ---------------------------------------------------------------------------
__global__ __launch_bounds__(256, 2) void interior_kernel(
    const float* __restrict__ attn_bias,
    const float* __restrict__ angle,
    const float* __restrict__ dists,
    const float* __restrict__ ang_w1, const float* __restrict__ ang_b1,
    const float* __restrict__ ang_w2, const float* __restrict__ ang_b2,
    const float* __restrict__ md_w1,  const float* __restrict__ md_b1,
    const float* __restrict__ md_w2,  const float* __restrict__ md_b2,
    const float* __restrict__ virt,
    float* __restrict__ out)
{
    __shared__ uint2  wfrag[32][32];                       // [m*8+s*4+n][lane]
    __shared__ float2 bfr[3][4][32];                       // [mat][n][lane]
    __shared__ __align__(128) unsigned char mbuf[8][2560]; // per-warp ldmatrix buf

    const int tid = threadIdx.x;

    for (int e = tid; e < 1024; e += 256) {
        const int p = e >> 5, ln = e & 31;
        const int m = p >> 3, s = (p >> 2) & 1, n = p & 3;
        const int q = ln >> 2, tq4 = ln & 3;
        const int r0 = s * 16 + tq4 * 2;
        const int c  = n * 8 + q;
        const float* w = (m == 0) ? ang_w1 : (m == 1) ? md_w1 : (m == 2) ? ang_w2 : md_w2;
        const bool pad = (m < 2);
        float v00 = (pad && r0     >= 28) ? 0.f : w[(r0)     * 32 + c];
        float v01 = (pad && r0 + 1 >= 28) ? 0.f : w[(r0 + 1) * 32 + c];
        float v10 = (pad && r0 + 8 >= 28) ? 0.f : w[(r0 + 8) * 32 + c];
        float v11 = (pad && r0 + 9 >= 28) ? 0.f : w[(r0 + 9) * 32 + c];
        wfrag[p][ln] = make_uint2(packbf(v00, v01), packbf(v10, v11));
    }
    for (int e = tid; e < 384; e += 256) {
        const int mat = e >> 7, rem = e & 127, n = rem >> 5, ln = rem & 31;
        const int i2 = n * 8 + (ln & 3) * 2;
        float lo, hi;
        if (mat == 0)      { lo = ang_b1[i2];              hi = ang_b1[i2 + 1]; }
        else if (mat == 1) { lo = md_b1[i2];               hi = md_b1[i2 + 1]; }
        else               { lo = ang_b2[i2] + md_b2[i2];  hi = ang_b2[i2 + 1] + md_b2[i2 + 1]; }
        bfr[mat][n][ln] = make_float2(lo, hi);
    }
    *(float2*)(mbuf[tid >> 5] + (tid & 31) * 80 + 56) = make_float2(0.f, 0.f);
    __syncthreads();

    const int lane = tid & 31;
    const int warp = tid >> 5;
    const int qid  = lane >> 2;
    const int tq   = lane & 3;

    const int bid = blockIdx.x;
    const int g = bid >> 9;
    const int i = (bid & 511) + 1;
    const size_t rowp = (size_t)(g * NN + (i - 1)) * NN * 28;
    const float* angRow  = angle + rowp;
    const float* dstRow  = dists + rowp;
    const float* attnRow = attn_bias + ((size_t)g * NP1 + i) * NP1;
    float* outRow = out + (size_t)g * HH * PLANE + (size_t)i * NP1;

    // ---- edge bucket for this row (warp-resident) ----
    const int ne = min(g_cnt[g * NP1 + i], CAP);
    const int bbase = (g * NP1 + i) * CAP;
    int eb0 = (lane      < ne) ? g_bucket[bbase + lane]      : -1;
    int eb1 = (lane + 32 < ne) ? g_bucket[bbase + lane + 32] : -1;
    int eb2 = (lane + 64 < ne) ? g_bucket[bbase + lane + 64] : -1;

    const uint32_t abase = (uint32_t)__cvta_generic_to_shared(mbuf[warp]);
    const uint32_t dbase = abase + 1280;
    const uint32_t lm_off = (uint32_t)((lane & 15) * 80 + ((lane >> 4) << 4));

    float2 ra[7], rd[7];
    float at0, at1;
    {
        const float2* a2 = (const float2*)angRow + (size_t)(warp * 16) * 14;
        const float2* d2 = (const float2*)dstRow + (size_t)(warp * 16) * 14;
#pragma unroll
        for (int k = 0; k < 7; k++) {
            ra[k] = __ldcs(a2 + lane + 32 * k);
            rd[k] = __ldcs(d2 + lane + 32 * k);
        }
        at0 = __ldg(attnRow + warp * 16 + 1 + qid);
        at1 = __ldg(attnRow + warp * 16 + 9 + qid);
    }

#pragma unroll
    for (int it = 0; it < 4; it++) {
        const int t  = warp + it * 8;
        const int j0 = t * 16;

        __syncwarp();
#pragma unroll
        for (int k = 0; k < 7; k++) {
            const int f   = lane + 32 * k;
            const int row = f / 14;
            const int c   = f - row * 14;
            const int off = row * 80 + c * 4;
            *(unsigned*)(mbuf[warp] + off)        = packbf2(ra[k]);
            *(unsigned*)(mbuf[warp] + 1280 + off) = packbf2(rd[k]);
        }
        __syncwarp();

        unsigned Aa0[4], Aa1[4], Ad0[4], Ad1[4];
        ldm4(Aa0, abase + lm_off);
        ldm4(Aa1, abase + lm_off + 32);
        ldm4(Ad0, dbase + lm_off);
        ldm4(Ad1, dbase + lm_off + 32);

        const float cat0 = at0, cat1 = at1;

        if (it < 3) {
            const int jn = (t + 8) * 16;
            const float2* a2 = (const float2*)angRow + (size_t)jn * 14;
            const float2* d2 = (const float2*)dstRow + (size_t)jn * 14;
#pragma unroll
            for (int k = 0; k < 7; k++) {
                ra[k] = __ldcs(a2 + lane + 32 * k);
                rd[k] = __ldcs(d2 + lane + 32 * k);
            }
            at0 = __ldg(attnRow + jn + 1 + qid);
            at1 = __ldg(attnRow + jn + 9 + qid);
        }

        float c2[4][4];
#pragma unroll
        for (int n = 0; n < 4; n++) {
            const float2 bb = bfr[2][n][lane];
            c2[n][0] = bb.x; c2[n][1] = bb.y; c2[n][2] = bb.x; c2[n][3] = bb.y;
        }

        float hh[4][4];
        unsigned A[4];

        // MLP(angle) layer 1
#pragma unroll
        for (int n = 0; n < 4; n++) {
            const float2 bb = bfr[0][n][lane];
            hh[n][0] = bb.x; hh[n][1] = bb.y; hh[n][2] = bb.x; hh[n][3] = bb.y;
        }
#pragma unroll
        for (int n = 0; n < 4; n++) mma_bf16(hh[n], Aa0, wfrag[0 + n][lane]);
#pragma unroll
        for (int n = 0; n < 4; n++) mma_bf16(hh[n], Aa1, wfrag[4 + n][lane]);
        // relu -> layer 2 (ang_w2)
#pragma unroll
        for (int ss = 0; ss < 2; ss++) {
            A[0] = packbf(fmaxf(hh[2*ss][0], 0.f), fmaxf(hh[2*ss][1], 0.f));
            A[1] = packbf(fmaxf(hh[2*ss][2], 0.f), fmaxf(hh[2*ss][3], 0.f));
            A[2] = packbf(fmaxf(hh[2*ss+1][0], 0.f), fmaxf(hh[2*ss+1][1], 0.f));
            A[3] = packbf(fmaxf(hh[2*ss+1][2], 0.f), fmaxf(hh[2*ss+1][3], 0.f));
#pragma unroll
            for (int n = 0; n < 4; n++) mma_bf16(c2[n], A, wfrag[16 + ss * 4 + n][lane]);
        }

        // MLP(dists) layer 1
#pragma unroll
        for (int n = 0; n < 4; n++) {
            const float2 bb = bfr[1][n][lane];
            hh[n][0] = bb.x; hh[n][1] = bb.y; hh[n][2] = bb.x; hh[n][3] = bb.y;
        }
#pragma unroll
        for (int n = 0; n < 4; n++) mma_bf16(hh[n], Ad0, wfrag[8 + n][lane]);
#pragma unroll
        for (int n = 0; n < 4; n++) mma_bf16(hh[n], Ad1, wfrag[12 + n][lane]);
        // relu -> layer 2 (md_w2)
#pragma unroll
        for (int ss = 0; ss < 2; ss++) {
            A[0] = packbf(fmaxf(hh[2*ss][0], 0.f), fmaxf(hh[2*ss][1], 0.f));
            A[1] = packbf(fmaxf(hh[2*ss][2], 0.f), fmaxf(hh[2*ss][3], 0.f));
            A[2] = packbf(fmaxf(hh[2*ss+1][0], 0.f), fmaxf(hh[2*ss+1][1], 0.f));
            A[3] = packbf(fmaxf(hh[2*ss+1][2], 0.f), fmaxf(hh[2*ss+1][3], 0.f));
#pragma unroll
            for (int n = 0; n < 4; n++) mma_bf16(c2[n], A, wfrag[24 + ss * 4 + n][lane]);
        }

        // ---- fused edge contributions for this 16-j window ----
        if (ne) {
#pragma unroll
            for (int half = 0; half < 3; half++) {
                const int ereg = (half == 0) ? eb0 : (half == 1) ? eb1 : eb2;
                unsigned m = __ballot_sync(0xffffffffu,
                    ereg >= 0 && (unsigned)((ereg >> 13) - 1 - j0) < 16u);
                while (m) {
                    const int k = __ffs(m) - 1;
                    m &= m - 1;
                    const int ent = __shfl_sync(0xffffffffu, ereg, k);
                    const int rel = (ent >> 13) - 1 - j0;     // 0..15
                    const int e   = ent & (NE - 1);
                    const float2* vp = (const float2*)(g_vals + (size_t)(g * NE + e) * HH);
                    if (rel < 8) {
                        if (qid == rel) {
#pragma unroll
                            for (int n = 0; n < 4; n++) {
                                const float2 v = vp[n * 4 + tq];
                                c2[n][0] += v.x; c2[n][1] += v.y;
                            }
                        }
                    } else {
                        if (qid == rel - 8) {
#pragma unroll
                            for (int n = 0; n < 4; n++) {
                                const float2 v = vp[n * 4 + tq];
                                c2[n][2] += v.x; c2[n][3] += v.y;
                            }
                        }
                    }
                }
            }
        }

        // ---- add attn_bias base, store (streaming: write-once data) ----
#pragma unroll
        for (int n = 0; n < 4; n++) {
            float* o = outRow + (size_t)(n * 8 + tq * 2) * PLANE;
            __stcs(o + j0 + 1 + qid,         c2[n][0] + cat0);
            __stcs(o + PLANE + j0 + 1 + qid, c2[n][1] + cat0);
            __stcs(o + j0 + 9 + qid,         c2[n][2] + cat1);
            __stcs(o + PLANE + j0 + 9 + qid, c2[n][3] + cat1);
        }
    }

    // ---- fused col-0 (attn + virt) for this row; self-clean bucket count ----
    if (warp == 0) {
        const float a0 = attnRow[0];
        __stcs(outRow + (size_t)lane * PLANE, a0 + virt[lane]);
    }
    if (tid == 0) g_cnt[g * NP1 + i] = 0;
}

// ---------------------------------------------------------------------------
// Kernel B: row-0 fill: out[g,h,0,j] = attn[g,0,j] + virt[h]  (coalesced)
// ---------------------------------------------------------------------------
__global__ __launch_bounds__(256) void row0_kernel(
    const float* __restrict__ attn_bias,
    const float* __restrict__ virt,
    float* __restrict__ out)
{
    const int idx = blockIdx.x * 256 + threadIdx.x;
    const int total = NG * HH * NP1;
    if (idx >= total) return;
    const int j  = idx % NP1;
    const int gh = idx / NP1;
    const int h = gh & 31;
    const int g = gh >> 5;
    __stcs(out + ((size_t)(g * HH + h)) * PLANE + j,
           attn_bias[(size_t)g * PLANE + j] + virt[h]);
}

// ---------------------------------------------------------------------------
extern "C" void kernel_launch(void* const* d_in, const int* in_sizes, int n_in,
                              void* d_out, int out_size) {
    const float* edge_feat  = (const float*)d_in[0];
    const int*   edge_index = (const int*)d_in[1];
    const int*   edge_mask  = (const int*)d_in[2];
    const int*   num_lig    = (const int*)d_in[3];
    const float* attn_bias  = (const float*)d_in[4];
    const float* angle      = (const float*)d_in[5];
    const float* dists      = (const float*)d_in[6];
    // d_in[7] node_feat unused
    const float* struct_emb = (const float*)d_in[8];
    const float* plip_lig   = (const float*)d_in[9];
    const float* plip_prot  = (const float*)d_in[10];
    const float* plip_inter = (const float*)d_in[11];
    const float* dist_w1 = (const float*)d_in[12];
    const float* dist_b1 = (const float*)d_in[13];
    const float* dist_w2 = (const float*)d_in[14];
    const float* dist_b2 = (const float*)d_in[15];
    const float* ang_w1  = (const float*)d_in[16];
    const float* ang_b1  = (const float*)d_in[17];
    const float* ang_w2  = (const float*)d_in[18];
    const float* ang_b2  = (const float*)d_in[19];
    const float* md_w1   = (const float*)d_in[20];
    const float* md_b1   = (const float*)d_in[21];
    const float* md_w2   = (const float*)d_in[22];
    const float* md_b2   = (const float*)d_in[23];
    const float* virt    = (const float*)d_in[24];
    float* out = (float*)d_out;

    // efill (vals + buckets) -> interior (consumes + self-cleans + col0) -> row0
    efill_kernel<<<NG * NE / 64, 256>>>(edge_feat, edge_index, edge_mask, num_lig,
                                        struct_emb, plip_lig, plip_prot, plip_inter,
                                        dist_w1, dist_b1, dist_w2, dist_b2);
    interior_kernel<<<NG * NN, 256>>>(attn_bias, angle, dists,
                                      ang_w1, ang_b1, ang_w2, ang_b2,
                                      md_w1, md_b1, md_w2, md_b2, virt, out);
    row0_kernel<<<(NG * HH * NP1 + 255) / 256, 256>>>(attn_bias, virt, out);
}

// round 13
// speedup vs baseline: 1.2133x; 1.0014x over previous
#include <cuda_runtime.h>
#include <cuda_bf16.h>
#include <cstdint>

#define NG 8
#define NE 8192
#define NN 512
#define NP1 513
#define HH 32
#define PLANE (513*513)
#define CAP 96          // per-(g,row) edge bucket capacity (max expected ~38)

// ---------------------------------------------------------------------------
// scratch (static __device__ arrays; zero-initialized at module load).
// g_cnt is self-cleaning: interior zeros each entry after consuming it, so
// every execution (correctness run, each graph replay) starts from zeros.
// ---------------------------------------------------------------------------
__device__ float g_vals[NG * NE * HH];          // per-edge 32-head vector (8.4MB)
__device__ int   g_bucket[NG * NP1 * CAP];      // packed (e | col<<13)
__device__ int   g_cnt[NG * NP1];               // bucket counts

// ---------------------------------------------------------------------------
// helpers
// ---------------------------------------------------------------------------
__device__ __forceinline__ unsigned packbf(float lo, float hi) {
    __nv_bfloat162 t = __floats2bfloat162_rn(lo, hi);
    return *reinterpret_cast<unsigned*>(&t);
}
__device__ __forceinline__ unsigned packbf2(float2 v) { return packbf(v.x, v.y); }

__device__ __forceinline__ void mma_bf16(float* c, const unsigned* a, uint2 b) {
    asm volatile(
        "mma.sync.aligned.m16n8k16.row.col.f32.bf16.bf16.f32 "
        "{%0,%1,%2,%3}, {%4,%5,%6,%7}, {%8,%9}, {%0,%1,%2,%3};\n"
        : "+f"(c[0]), "+f"(c[1]), "+f"(c[2]), "+f"(c[3])
        : "r"(a[0]), "r"(a[1]), "r"(a[2]), "r"(a[3]), "r"(b.x), "r"(b.y));
}

__device__ __forceinline__ void ldm4(unsigned* r, uint32_t addr) {
    asm volatile("ldmatrix.sync.aligned.m8n8.x4.shared.b16 {%0,%1,%2,%3}, [%4];"
                 : "=r"(r[0]), "=r"(r[1]), "=r"(r[2]), "=r"(r[3]) : "r"(addr));
}

// ---------------------------------------------------------------------------
// efill: per-edge MLP + embedding -> g_vals; push packed entry into row bucket.
// One warp handles 8 edges; lane = head. Restructured for ILP: all 8 hid
// values computed first, then one 32-step loop with 8 independent fma chains.
// edge_mask is int32 (jax bool).
// ---------------------------------------------------------------------------
__global__ __launch_bounds__(256) void efill_kernel(
    const float* __restrict__ edge_feat,
    const int*   __restrict__ edge_index,
    const int*   __restrict__ edge_mask,
    const int*   __restrict__ num_ligand_atoms,
    const float* __restrict__ struct_emb,
    const float* __restrict__ plip_lig,
    const float* __restrict__ plip_prot,
    const float* __restrict__ plip_inter,
    const float* __restrict__ dist_w1, const float* __restrict__ dist_b1,
    const float* __restrict__ dist_w2, const float* __restrict__ dist_b2)
{
    __shared__ float s_w2[1024];
    __shared__ float s_w1[32], s_b1[32], s_b2[32];
    const int tid = threadIdx.x;
    for (int idx = tid; idx < 1024; idx += 256) s_w2[idx] = dist_w2[idx];
    if (tid < 32) {
        s_w1[tid] = dist_w1[tid];
        s_b1[tid] = dist_b1[tid];
        s_b2[tid] = dist_b2[tid];
    }
    __syncthreads();

    const int warp = tid >> 5;
    const int lane = tid & 31;
    const int ebase = blockIdx.x * 64 + warp * 8;   // grid exact: NG*NE/64 blocks
    const int g = ebase >> 13;                       // same g for all 8 edges
    int nl = num_ligand_atoms[g];
    nl = nl > 1 ? nl : 1;

    float hid[8], y[8];
    int   srcv[8], tgtv[8];
    unsigned actmask = 0;

    // ---- phase 1: per-edge hid + embedding select (independent work) ----
#pragma unroll
    for (int s = 0; s < 8; s++) {
        const int eid = ebase + s;
        hid[s] = 0.f;
        y[s]   = s_b2[lane];
        srcv[s] = 0; tgtv[s] = 0;
        if (edge_mask[eid] != 0) {
            actmask |= 1u << s;
            const int e = eid & (NE - 1);
            const float4 ef = reinterpret_cast<const float4*>(edge_feat)[eid];
            const int t0 = (int)ef.x;
            const int t1 = (int)ef.y;
            const int t2 = (int)ef.z;
            const float d = ef.w;
            srcv[s] = edge_index[(size_t)g * 2 * NE + e];
            tgtv[s] = edge_index[(size_t)g * 2 * NE + NE + e];
            const bool sl = (srcv[s] > 0) && (srcv[s] < nl);
            const bool tl = (tgtv[s] > 0) && (tgtv[s] < nl);
            hid[s] = fmaxf(fmaf(d, s_w1[lane], s_b1[lane]), 0.f);
            float sel = 0.f;
            if (t0 <= 1) {
                int si = t0 * 4 + t1 * 2 + t2;
                si = si < 0 ? 0 : (si > 19 ? 19 : si);
                sel = struct_emb[si * 32 + lane];
            } else if (t0 == 5) {
                int pi = t1 < 0 ? 0 : (t1 > 14 ? 14 : t1);
                const float* tab = (sl && tl) ? plip_lig
                                 : ((!sl && !tl) ? plip_prot : plip_inter);
                sel = tab[pi * 32 + lane];
            }
            y[s] += sel;
        }
    }

    // ---- phase 2: layer-2 matvec, 8 independent chains (8-way ILP) ----
#pragma unroll
    for (int m = 0; m < 32; m++) {
        const float w = s_w2[m * 32 + lane];
#pragma unroll
        for (int s = 0; s < 8; s++)
            y[s] = fmaf(__shfl_sync(0xffffffffu, hid[s], m), w, y[s]);
    }

    // ---- phase 3: stores + bucket pushes ----
#pragma unroll
    for (int s = 0; s < 8; s++) {
        if (!(actmask & (1u << s))) continue;
        const int eid = ebase + s;
        const int e = eid & (NE - 1);
        g_vals[(size_t)eid * HH + lane] = y[s];      // coalesced 128B
        if (lane == 0) {
            const int row = srcv[s] + 1;              // 1..512
            const int slot = atomicAdd(&g_cnt[g * NP1 + row], 1);
            if (slot < CAP)
                g_bucket[(g * NP1 + row) * CAP + slot] = e | ((tgtv[s] + 1) << 13);
        }
    }
}

// ---------------------------------------------------------------------------
// Kernel A: interior fill  out[g,h,i,j] for i,j in [1,512]  (R8 structure)
// + fused edge contributions + col-0 (attn + virt) + self-cleaning g_cnt.
// ---------------------------------------------------------------------------
__global__ __launch_bounds__(256, 2) void interior_kernel(
    const float* __restrict__ attn_bias,
    const float* __restrict__ angle,
    const float* __restrict__ dists,
    const float* __restrict__ ang_w1, const float* __restrict__ ang_b1,
    const float* __restrict__ ang_w2, const float* __restrict__ ang_b2,
    const float* __restrict__ md_w1,  const float* __restrict__ md_b1,
    const float* __restrict__ md_w2,  const float* __restrict__ md_b2,
    const float* __restrict__ virt,
    float* __restrict__ out)
{
    __shared__ uint2  wfrag[32][32];                       // [m*8+s*4+n][lane]
    __shared__ float2 bfr[3][4][32];                       // [mat][n][lane]
    __shared__ __align__(128) unsigned char mbuf[8][2560]; // per-warp ldmatrix buf

    const int tid = threadIdx.x;

    for (int e = tid; e < 1024; e += 256) {
        const int p = e >> 5, ln = e & 31;
        const int m = p >> 3, s = (p >> 2) & 1, n = p & 3;
        const int q = ln >> 2, tq4 = ln & 3;
        const int r0 = s * 16 + tq4 * 2;
        const int c  = n * 8 + q;
        const float* w = (m == 0) ? ang_w1 : (m == 1) ? md_w1 : (m == 2) ? ang_w2 : md_w2;
        const bool pad = (m < 2);
        float v00 = (pad && r0     >= 28) ? 0.f : w[(r0)     * 32 + c];
        float v01 = (pad && r0 + 1 >= 28) ? 0.f : w[(r0 + 1) * 32 + c];
        float v10 = (pad && r0 + 8 >= 28) ? 0.f : w[(r0 + 8) * 32 + c];
        float v11 = (pad && r0 + 9 >= 28) ? 0.f : w[(r0 + 9) * 32 + c];
        wfrag[p][ln] = make_uint2(packbf(v00, v01), packbf(v10, v11));
    }
    for (int e = tid; e < 384; e += 256) {
        const int mat = e >> 7, rem = e & 127, n = rem >> 5, ln = rem & 31;
        const int i2 = n * 8 + (ln & 3) * 2;
        float lo, hi;
        if (mat == 0)      { lo = ang_b1[i2];              hi = ang_b1[i2 + 1]; }
        else if (mat == 1) { lo = md_b1[i2];               hi = md_b1[i2 + 1]; }
        else               { lo = ang_b2[i2] + md_b2[i2];  hi = ang_b2[i2 + 1] + md_b2[i2 + 1]; }
        bfr[mat][n][ln] = make_float2(lo, hi);
    }
    *(float2*)(mbuf[tid >> 5] + (tid & 31) * 80 + 56) = make_float2(0.f, 0.f);
    __syncthreads();

    const int lane = tid & 31;
    const int warp = tid >> 5;
    const int qid  = lane >> 2;
    const int tq   = lane & 3;

    const int bid = blockIdx.x;
    const int g = bid >> 9;
    const int i = (bid & 511) + 1;
    const size_t rowp = (size_t)(g * NN + (i - 1)) * NN * 28;
    const float* angRow  = angle + rowp;
    const float* dstRow  = dists + rowp;
    const float* attnRow = attn_bias + ((size_t)g * NP1 + i) * NP1;
    float* outRow = out + (size_t)g * HH * PLANE + (size_t)i * NP1;

    // ---- edge bucket for this row (warp-resident) ----
    const int ne = min(g_cnt[g * NP1 + i], CAP);
    const int bbase = (g * NP1 + i) * CAP;
    int eb0 = (lane      < ne) ? g_bucket[bbase + lane]      : -1;
    int eb1 = (lane + 32 < ne) ? g_bucket[bbase + lane + 32] : -1;
    int eb2 = (lane + 64 < ne) ? g_bucket[bbase + lane + 64] : -1;

    const uint32_t abase = (uint32_t)__cvta_generic_to_shared(mbuf[warp]);
    const uint32_t dbase = abase + 1280;
    const uint32_t lm_off = (uint32_t)((lane & 15) * 80 + ((lane >> 4) << 4));

    float2 ra[7], rd[7];
    float at0, at1;
    {
        const float2* a2 = (const float2*)angRow + (size_t)(warp * 16) * 14;
        const float2* d2 = (const float2*)dstRow + (size_t)(warp * 16) * 14;
#pragma unroll
        for (int k = 0; k < 7; k++) {
            ra[k] = __ldcs(a2 + lane + 32 * k);
            rd[k] = __ldcs(d2 + lane + 32 * k);
        }
        at0 = __ldg(attnRow + warp * 16 + 1 + qid);
        at1 = __ldg(attnRow + warp * 16 + 9 + qid);
    }

#pragma unroll
    for (int it = 0; it < 4; it++) {
        const int t  = warp + it * 8;
        const int j0 = t * 16;

        __syncwarp();
#pragma unroll
        for (int k = 0; k < 7; k++) {
            const int f   = lane + 32 * k;
            const int row = f / 14;
            const int c   = f - row * 14;
            const int off = row * 80 + c * 4;
            *(unsigned*)(mbuf[warp] + off)        = packbf2(ra[k]);
            *(unsigned*)(mbuf[warp] + 1280 + off) = packbf2(rd[k]);
        }
        __syncwarp();

        unsigned Aa0[4], Aa1[4], Ad0[4], Ad1[4];
        ldm4(Aa0, abase + lm_off);
        ldm4(Aa1, abase + lm_off + 32);
        ldm4(Ad0, dbase + lm_off);
        ldm4(Ad1, dbase + lm_off + 32);

        const float cat0 = at0, cat1 = at1;

        if (it < 3) {
            const int jn = (t + 8) * 16;
            const float2* a2 = (const float2*)angRow + (size_t)jn * 14;
            const float2* d2 = (const float2*)dstRow + (size_t)jn * 14;
#pragma unroll
            for (int k = 0; k < 7; k++) {
                ra[k] = __ldcs(a2 + lane + 32 * k);
                rd[k] = __ldcs(d2 + lane + 32 * k);
            }
            at0 = __ldg(attnRow + jn + 1 + qid);
            at1 = __ldg(attnRow + jn + 9 + qid);
        }

        float c2[4][4];
#pragma unroll
        for (int n = 0; n < 4; n++) {
            const float2 bb = bfr[2][n][lane];
            c2[n][0] = bb.x; c2[n][1] = bb.y; c2[n][2] = bb.x; c2[n][3] = bb.y;
        }

        float hh[4][4];
        unsigned A[4];

        // MLP(angle) layer 1
#pragma unroll
        for (int n = 0; n < 4; n++) {
            const float2 bb = bfr[0][n][lane];
            hh[n][0] = bb.x; hh[n][1] = bb.y; hh[n][2] = bb.x; hh[n][3] = bb.y;
        }
#pragma unroll
        for (int n = 0; n < 4; n++) mma_bf16(hh[n], Aa0, wfrag[0 + n][lane]);
#pragma unroll
        for (int n = 0; n < 4; n++) mma_bf16(hh[n], Aa1, wfrag[4 + n][lane]);
        // relu -> layer 2 (ang_w2)
#pragma unroll
        for (int ss = 0; ss < 2; ss++) {
            A[0] = packbf(fmaxf(hh[2*ss][0], 0.f), fmaxf(hh[2*ss][1], 0.f));
            A[1] = packbf(fmaxf(hh[2*ss][2], 0.f), fmaxf(hh[2*ss][3], 0.f));
            A[2] = packbf(fmaxf(hh[2*ss+1][0], 0.f), fmaxf(hh[2*ss+1][1], 0.f));
            A[3] = packbf(fmaxf(hh[2*ss+1][2], 0.f), fmaxf(hh[2*ss+1][3], 0.f));
#pragma unroll
            for (int n = 0; n < 4; n++) mma_bf16(c2[n], A, wfrag[16 + ss * 4 + n][lane]);
        }

        // MLP(dists) layer 1
#pragma unroll
        for (int n = 0; n < 4; n++) {
            const float2 bb = bfr[1][n][lane];
            hh[n][0] = bb.x; hh[n][1] = bb.y; hh[n][2] = bb.x; hh[n][3] = bb.y;
        }
#pragma unroll
        for (int n = 0; n < 4; n++) mma_bf16(hh[n], Ad0, wfrag[8 + n][lane]);
#pragma unroll
        for (int n = 0; n < 4; n++) mma_bf16(hh[n], Ad1, wfrag[12 + n][lane]);
        // relu -> layer 2 (md_w2)
#pragma unroll
        for (int ss = 0; ss < 2; ss++) {
            A[0] = packbf(fmaxf(hh[2*ss][0], 0.f), fmaxf(hh[2*ss][1], 0.f));
            A[1] = packbf(fmaxf(hh[2*ss][2], 0.f), fmaxf(hh[2*ss][3], 0.f));
            A[2] = packbf(fmaxf(hh[2*ss+1][0], 0.f), fmaxf(hh[2*ss+1][1], 0.f));
            A[3] = packbf(fmaxf(hh[2*ss+1][2], 0.f), fmaxf(hh[2*ss+1][3], 0.f));
#pragma unroll
            for (int n = 0; n < 4; n++) mma_bf16(c2[n], A, wfrag[24 + ss * 4 + n][lane]);
        }

        // ---- fused edge contributions for this 16-j window ----
        if (ne) {
#pragma unroll
            for (int half = 0; half < 3; half++) {
                const int ereg = (half == 0) ? eb0 : (half == 1) ? eb1 : eb2;
                unsigned m = __ballot_sync(0xffffffffu,
                    ereg >= 0 && (unsigned)((ereg >> 13) - 1 - j0) < 16u);
                while (m) {
                    const int k = __ffs(m) - 1;
                    m &= m - 1;
                    const int ent = __shfl_sync(0xffffffffu, ereg, k);
                    const int rel = (ent >> 13) - 1 - j0;     // 0..15
                    const int e   = ent & (NE - 1);
                    const float2* vp = (const float2*)(g_vals + (size_t)(g * NE + e) * HH);
                    if (rel < 8) {
                        if (qid == rel) {
#pragma unroll
                            for (int n = 0; n < 4; n++) {
                                const float2 v = vp[n * 4 + tq];
                                c2[n][0] += v.x; c2[n][1] += v.y;
                            }
                        }
                    } else {
                        if (qid == rel - 8) {
#pragma unroll
                            for (int n = 0; n < 4; n++) {
                                const float2 v = vp[n * 4 + tq];
                                c2[n][2] += v.x; c2[n][3] += v.y;
                            }
                        }
                    }
                }
            }
        }

        // ---- add attn_bias base, store (streaming: write-once data) ----
#pragma unroll
        for (int n = 0; n < 4; n++) {
            float* o = outRow + (size_t)(n * 8 + tq * 2) * PLANE;
            __stcs(o + j0 + 1 + qid,         c2[n][0] + cat0);
            __stcs(o + PLANE + j0 + 1 + qid, c2[n][1] + cat0);
            __stcs(o + j0 + 9 + qid,         c2[n][2] + cat1);
            __stcs(o + PLANE + j0 + 9 + qid, c2[n][3] + cat1);
        }
    }

    // ---- fused col-0 (attn + virt) for this row; self-clean bucket count ----
    if (warp == 0) {
        const float a0 = attnRow[0];
        __stcs(outRow + (size_t)lane * PLANE, a0 + virt[lane]);
    }
    if (tid == 0) g_cnt[g * NP1 + i] = 0;
}

// ---------------------------------------------------------------------------
// Kernel B: row-0 fill: out[g,h,0,j] = attn[g,0,j] + virt[h]  (coalesced)
// ---------------------------------------------------------------------------
__global__ __launch_bounds__(256) void row0_kernel(
    const float* __restrict__ attn_bias,
    const float* __restrict__ virt,
    float* __restrict__ out)
{
    const int idx = blockIdx.x * 256 + threadIdx.x;
    const int total = NG * HH * NP1;
    if (idx >= total) return;
    const int j  = idx % NP1;
    const int gh = idx / NP1;
    const int h = gh & 31;
    const int g = gh >> 5;
    __stcs(out + ((size_t)(g * HH + h)) * PLANE + j,
           attn_bias[(size_t)g * PLANE + j] + virt[h]);
}

// ---------------------------------------------------------------------------
extern "C" void kernel_launch(void* const* d_in, const int* in_sizes, int n_in,
                              void* d_out, int out_size) {
    const float* edge_feat  = (const float*)d_in[0];
    const int*   edge_index = (const int*)d_in[1];
    const int*   edge_mask  = (const int*)d_in[2];
    const int*   num_lig    = (const int*)d_in[3];
    const float* attn_bias  = (const float*)d_in[4];
    const float* angle      = (const float*)d_in[5];
    const float* dists      = (const float*)d_in[6];
    // d_in[7] node_feat unused
    const float* struct_emb = (const float*)d_in[8];
    const float* plip_lig   = (const float*)d_in[9];
    const float* plip_prot  = (const float*)d_in[10];
    const float* plip_inter = (const float*)d_in[11];
    const float* dist_w1 = (const float*)d_in[12];
    const float* dist_b1 = (const float*)d_in[13];
    const float* dist_w2 = (const float*)d_in[14];
    const float* dist_b2 = (const float*)d_in[15];
    const float* ang_w1  = (const float*)d_in[16];
    const float* ang_b1  = (const float*)d_in[17];
    const float* ang_w2  = (const float*)d_in[18];
    const float* ang_b2  = (const float*)d_in[19];
    const float* md_w1   = (const float*)d_in[20];
    const float* md_b1   = (const float*)d_in[21];
    const float* md_w2   = (const float*)d_in[22];
    const float* md_b2   = (const float*)d_in[23];
    const float* virt    = (const float*)d_in[24];
    float* out = (float*)d_out;

    // efill (vals + buckets) -> interior (consumes + self-cleans + col0) -> row0
    efill_kernel<<<NG * NE / 64, 256>>>(edge_feat, edge_index, edge_mask, num_lig,
                                        struct_emb, plip_lig, plip_prot, plip_inter,
                                        dist_w1, dist_b1, dist_w2, dist_b2);
    interior_kernel<<<NG * NN, 256>>>(attn_bias, angle, dists,
                                      ang_w1, ang_b1, ang_w2, ang_b2,
                                      md_w1, md_b1, md_w2, md_b2, virt, out);
    row0_kernel<<<(NG * HH * NP1 + 255) / 256, 256>>>(attn_bias, virt, out);
}

// round 15
// speedup vs baseline: 1.3001x; 1.0716x over previous
#include <cuda_runtime.h>
#include <cuda_bf16.h>
#include <cstdint>

#define NG 8
#define NE 8192
#define NN 512
#define NP1 513
#define HH 32
#define PLANE (513*513)
#define CAP 96          // per-(g,row) edge bucket capacity (max expected ~38)

// ---------------------------------------------------------------------------
// scratch (static __device__ arrays; zero-initialized at module load).
// g_cnt is self-cleaning: interior zeros each entry after consuming it, so
// every execution (correctness run, each graph replay) starts from zeros.
// ---------------------------------------------------------------------------
__device__ float g_vals[NG * NE * HH];          // per-edge 32-head vector (8.4MB)
__device__ int   g_bucket[NG * NP1 * CAP];      // packed (e | col<<13)
__device__ int   g_cnt[NG * NP1];               // bucket counts

// ---------------------------------------------------------------------------
// helpers
// ---------------------------------------------------------------------------
__device__ __forceinline__ unsigned packbf(float lo, float hi) {
    __nv_bfloat162 t = __floats2bfloat162_rn(lo, hi);
    return *reinterpret_cast<unsigned*>(&t);
}
__device__ __forceinline__ unsigned packbf2(float2 v) { return packbf(v.x, v.y); }

__device__ __forceinline__ void mma_bf16(float* c, const unsigned* a, uint2 b) {
    asm volatile(
        "mma.sync.aligned.m16n8k16.row.col.f32.bf16.bf16.f32 "
        "{%0,%1,%2,%3}, {%4,%5,%6,%7}, {%8,%9}, {%0,%1,%2,%3};\n"
        : "+f"(c[0]), "+f"(c[1]), "+f"(c[2]), "+f"(c[3])
        : "r"(a[0]), "r"(a[1]), "r"(a[2]), "r"(a[3]), "r"(b.x), "r"(b.y));
}

__device__ __forceinline__ void ldm4(unsigned* r, uint32_t addr) {
    asm volatile("ldmatrix.sync.aligned.m8n8.x4.shared.b16 {%0,%1,%2,%3}, [%4];"
                 : "=r"(r[0]), "=r"(r[1]), "=r"(r[2]), "=r"(r[3]) : "r"(addr));
}

// ---------------------------------------------------------------------------
// efill: per-edge MLP + embedding -> g_vals; push packed entry into row bucket.
// One warp = 16 edges; layer-2 matvec done as a 16x32x32 bf16 mma (same
// fragment mappings as the interior kernel). edge_mask is int32 (jax bool).
// ---------------------------------------------------------------------------
__global__ __launch_bounds__(256) void efill_kernel(
    const float* __restrict__ edge_feat,
    const int*   __restrict__ edge_index,
    const int*   __restrict__ edge_mask,
    const int*   __restrict__ num_ligand_atoms,
    const float* __restrict__ struct_emb,
    const float* __restrict__ plip_lig,
    const float* __restrict__ plip_prot,
    const float* __restrict__ plip_inter,
    const float* __restrict__ dist_w1, const float* __restrict__ dist_b1,
    const float* __restrict__ dist_w2, const float* __restrict__ dist_b2)
{
    __shared__ uint2 wf[2][4][32];           // layer-2 B-frags [kstep][n][lane]
    __shared__ float s_w1[32], s_b1[32], s_b2[32];

    const int tid = threadIdx.x;
    // build B fragments of dist_w2 (same builder as interior's wfrag)
    {
        const int p = tid >> 5, ln = tid & 31;
        const int s = p >> 2, n = p & 3;
        const int q = ln >> 2, t4 = ln & 3;
        const int r0 = s * 16 + t4 * 2;
        const int c  = n * 8 + q;
        wf[s][n][ln] = make_uint2(
            packbf(dist_w2[r0 * 32 + c],       dist_w2[(r0 + 1) * 32 + c]),
            packbf(dist_w2[(r0 + 8) * 32 + c], dist_w2[(r0 + 9) * 32 + c]));
    }
    if (tid < 32) {
        s_w1[tid] = dist_w1[tid];
        s_b1[tid] = dist_b1[tid];
        s_b2[tid] = dist_b2[tid];
    }
    __syncthreads();

    const int warp = tid >> 5;
    const int lane = tid & 31;
    const int qid  = lane >> 2;
    const int tq   = lane & 3;

    const int ebase = (blockIdx.x * 8 + warp) * 16;   // grid exact: NG*NE/128
    const int g = ebase >> 13;                         // same g for all 16 edges
    const int el0 = ebase & (NE - 1);                  // local edge base
    int nl = num_ligand_atoms[g];
    nl = nl > 1 ? nl : 1;

    // ---- lane-per-edge loads (lanes 0..15) ----
    int myact = 0, mysrc = 0, mytgt = 0;
    float myd = 0.f;
    const float* mysel = nullptr;
    if (lane < 16) {
        const int eid = ebase + lane;
        if (edge_mask[eid] != 0) {
            myact = 1;
            const int e = el0 + lane;
            const float4 ef = reinterpret_cast<const float4*>(edge_feat)[eid];
            const int t0 = (int)ef.x;
            const int t1 = (int)ef.y;
            const int t2 = (int)ef.z;
            myd = ef.w;
            mysrc = edge_index[(size_t)g * 2 * NE + e];
            mytgt = edge_index[(size_t)g * 2 * NE + NE + e];
            const bool sl = (mysrc > 0) && (mysrc < nl);
            const bool tl = (mytgt > 0) && (mytgt < nl);
            if (t0 <= 1) {
                int si = t0 * 4 + t1 * 2 + t2;
                si = si < 0 ? 0 : (si > 19 ? 19 : si);
                mysel = struct_emb + si * 32;
            } else if (t0 == 5) {
                int pi = t1 < 0 ? 0 : (t1 > 14 ? 14 : t1);
                const float* tab = (sl && tl) ? plip_lig
                                 : ((!sl && !tl) ? plip_prot : plip_inter);
                mysel = tab + pi * 32;
            }
        }
    }
    const unsigned full = 0xffffffffu;
    const unsigned amask = __ballot_sync(full, myact) & 0xffffu;
    if (!amask) return;                                  // whole tile masked

    const float d_lo = __shfl_sync(full, myd, qid);
    const float d_hi = __shfl_sync(full, myd, qid + 8);
    const float* plo = (const float*)__shfl_sync(full, (unsigned long long)mysel, qid);
    const float* phi = (const float*)__shfl_sync(full, (unsigned long long)mysel, qid + 8);

    // ---- C init: b2 + sel (fp32 exact) ----
    float c[4][4];
#pragma unroll
    for (int n = 0; n < 4; n++) {
        const int h0 = n * 8 + tq * 2;
        const float b0 = s_b2[h0], b1v = s_b2[h0 + 1];
        float2 vlo = plo ? *(const float2*)(plo + h0) : make_float2(0.f, 0.f);
        float2 vhi = phi ? *(const float2*)(phi + h0) : make_float2(0.f, 0.f);
        c[n][0] = b0 + vlo.x; c[n][1] = b1v + vlo.y;
        c[n][2] = b0 + vhi.x; c[n][3] = b1v + vhi.y;
    }

    // ---- layer 1 in A-frag layout + layer 2 mma ----
#pragma unroll
    for (int s = 0; s < 2; s++) {
        const int m0 = s * 16 + tq * 2;
        const int m2 = m0 + 8;
        unsigned A[4];
        A[0] = packbf(fmaxf(fmaf(d_lo, s_w1[m0], s_b1[m0]), 0.f),
                      fmaxf(fmaf(d_lo, s_w1[m0 + 1], s_b1[m0 + 1]), 0.f));
        A[1] = packbf(fmaxf(fmaf(d_hi, s_w1[m0], s_b1[m0]), 0.f),
                      fmaxf(fmaf(d_hi, s_w1[m0 + 1], s_b1[m0 + 1]), 0.f));
        A[2] = packbf(fmaxf(fmaf(d_lo, s_w1[m2], s_b1[m2]), 0.f),
                      fmaxf(fmaf(d_lo, s_w1[m2 + 1], s_b1[m2 + 1]), 0.f));
        A[3] = packbf(fmaxf(fmaf(d_hi, s_w1[m2], s_b1[m2]), 0.f),
                      fmaxf(fmaf(d_hi, s_w1[m2 + 1], s_b1[m2 + 1]), 0.f));
#pragma unroll
        for (int n = 0; n < 4; n++) mma_bf16(c[n], A, wf[s][n][lane]);
    }

    // ---- stores (mirror of interior's fused-edge read pattern) ----
    const int act_lo = (amask >> qid) & 1;
    const int act_hi = (amask >> (qid + 8)) & 1;
#pragma unroll
    for (int n = 0; n < 4; n++) {
        const int h0 = n * 8 + tq * 2;
        if (act_lo)
            *(float2*)&g_vals[(size_t)(ebase + qid) * HH + h0] =
                make_float2(c[n][0], c[n][1]);
        if (act_hi)
            *(float2*)&g_vals[(size_t)(ebase + qid + 8) * HH + h0] =
                make_float2(c[n][2], c[n][3]);
    }

    // ---- bucket pushes (lane-per-edge) ----
    if (lane < 16 && myact) {
        const int row = mysrc + 1;                 // 1..512
        const int slot = atomicAdd(&g_cnt[g * NP1 + row], 1);
        if (slot < CAP)
            g_bucket[(g * NP1 + row) * CAP + slot] = (el0 + lane) | ((mytgt + 1) << 13);
    }
}

// ---------------------------------------------------------------------------
// Kernel A: interior fill  out[g,h,i,j] for i,j in [1,512]  (R8 structure)
// + fused edge contributions + col-0 (attn + virt) + self-cleaning g_cnt.
// ---------------------------------------------------------------------------
__global__ __launch_bounds__(256, 2) void interior_kernel(
    const float* __restrict__ attn_bias,
    const float* __restrict__ angle,
    const float* __restrict__ dists,
    const float* __restrict__ ang_w1, const float* __restrict__ ang_b1,
    const float* __restrict__ ang_w2, const float* __restrict__ ang_b2,
    const float* __restrict__ md_w1,  const float* __restrict__ md_b1,
    const float* __restrict__ md_w2,  const float* __restrict__ md_b2,
    const float* __restrict__ virt,
    float* __restrict__ out)
{
    __shared__ uint2  wfrag[32][32];                       // [m*8+s*4+n][lane]
    __shared__ float2 bfr[3][4][32];                       // [mat][n][lane]
    __shared__ __align__(128) unsigned char mbuf[8][2560]; // per-warp ldmatrix buf

    const int tid = threadIdx.x;

    for (int e = tid; e < 1024; e += 256) {
        const int p = e >> 5, ln = e & 31;
        const int m = p >> 3, s = (p >> 2) & 1, n = p & 3;
        const int q = ln >> 2, tq4 = ln & 3;
        const int r0 = s * 16 + tq4 * 2;
        const int c  = n * 8 + q;
        const float* w = (m == 0) ? ang_w1 : (m == 1) ? md_w1 : (m == 2) ? ang_w2 : md_w2;
        const bool pad = (m < 2);
        float v00 = (pad && r0     >= 28) ? 0.f : w[(r0)     * 32 + c];
        float v01 = (pad && r0 + 1 >= 28) ? 0.f : w[(r0 + 1) * 32 + c];
        float v10 = (pad && r0 + 8 >= 28) ? 0.f : w[(r0 + 8) * 32 + c];
        float v11 = (pad && r0 + 9 >= 28) ? 0.f : w[(r0 + 9) * 32 + c];
        wfrag[p][ln] = make_uint2(packbf(v00, v01), packbf(v10, v11));
    }
    for (int e = tid; e < 384; e += 256) {
        const int mat = e >> 7, rem = e & 127, n = rem >> 5, ln = rem & 31;
        const int i2 = n * 8 + (ln & 3) * 2;
        float lo, hi;
        if (mat == 0)      { lo = ang_b1[i2];              hi = ang_b1[i2 + 1]; }
        else if (mat == 1) { lo = md_b1[i2];               hi = md_b1[i2 + 1]; }
        else               { lo = ang_b2[i2] + md_b2[i2];  hi = ang_b2[i2 + 1] + md_b2[i2 + 1]; }
        bfr[mat][n][ln] = make_float2(lo, hi);
    }
    *(float2*)(mbuf[tid >> 5] + (tid & 31) * 80 + 56) = make_float2(0.f, 0.f);
    __syncthreads();

    const int lane = tid & 31;
    const int warp = tid >> 5;
    const int qid  = lane >> 2;
    const int tq   = lane & 3;

    const int bid = blockIdx.x;
    const int g = bid >> 9;
    const int i = (bid & 511) + 1;
    const size_t rowp = (size_t)(g * NN + (i - 1)) * NN * 28;
    const float* angRow  = angle + rowp;
    const float* dstRow  = dists + rowp;
    const float* attnRow = attn_bias + ((size_t)g * NP1 + i) * NP1;
    float* outRow = out + (size_t)g * HH * PLANE + (size_t)i * NP1;

    // ---- edge bucket for this row (warp-resident) ----
    const int ne = min(g_cnt[g * NP1 + i], CAP);
    const int bbase = (g * NP1 + i) * CAP;
    int eb0 = (lane      < ne) ? g_bucket[bbase + lane]      : -1;
    int eb1 = (lane + 32 < ne) ? g_bucket[bbase + lane + 32] : -1;
    int eb2 = (lane + 64 < ne) ? g_bucket[bbase + lane + 64] : -1;

    const uint32_t abase = (uint32_t)__cvta_generic_to_shared(mbuf[warp]);
    const uint32_t dbase = abase + 1280;
    const uint32_t lm_off = (uint32_t)((lane & 15) * 80 + ((lane >> 4) << 4));

    float2 ra[7], rd[7];
    float at0, at1;
    {
        const float2* a2 = (const float2*)angRow + (size_t)(warp * 16) * 14;
        const float2* d2 = (const float2*)dstRow + (size_t)(warp * 16) * 14;
#pragma unroll
        for (int k = 0; k < 7; k++) {
            ra[k] = __ldcs(a2 + lane + 32 * k);
            rd[k] = __ldcs(d2 + lane + 32 * k);
        }
        at0 = __ldg(attnRow + warp * 16 + 1 + qid);
        at1 = __ldg(attnRow + warp * 16 + 9 + qid);
    }

#pragma unroll
    for (int it = 0; it < 4; it++) {
        const int t  = warp + it * 8;
        const int j0 = t * 16;

        __syncwarp();
#pragma unroll
        for (int k = 0; k < 7; k++) {
            const int f   = lane + 32 * k;
            const int row = f / 14;
            const int c   = f - row * 14;
            const int off = row * 80 + c * 4;
            *(unsigned*)(mbuf[warp] + off)        = packbf2(ra[k]);
            *(unsigned*)(mbuf[warp] + 1280 + off) = packbf2(rd[k]);
        }
        __syncwarp();

        unsigned Aa0[4], Aa1[4], Ad0[4], Ad1[4];
        ldm4(Aa0, abase + lm_off);
        ldm4(Aa1, abase + lm_off + 32);
        ldm4(Ad0, dbase + lm_off);
        ldm4(Ad1, dbase + lm_off + 32);

        const float cat0 = at0, cat1 = at1;

        if (it < 3) {
            const int jn = (t + 8) * 16;
            const float2* a2 = (const float2*)angRow + (size_t)jn * 14;
            const float2* d2 = (const float2*)dstRow + (size_t)jn * 14;
#pragma unroll
            for (int k = 0; k < 7; k++) {
                ra[k] = __ldcs(a2 + lane + 32 * k);
                rd[k] = __ldcs(d2 + lane + 32 * k);
            }
            at0 = __ldg(attnRow + jn + 1 + qid);
            at1 = __ldg(attnRow + jn + 9 + qid);
        }

        float c2[4][4];
#pragma unroll
        for (int n = 0; n < 4; n++) {
            const float2 bb = bfr[2][n][lane];
            c2[n][0] = bb.x; c2[n][1] = bb.y; c2[n][2] = bb.x; c2[n][3] = bb.y;
        }

        float hh[4][4];
        unsigned A[4];

        // MLP(angle) layer 1
#pragma unroll
        for (int n = 0; n < 4; n++) {
            const float2 bb = bfr[0][n][lane];
            hh[n][0] = bb.x; hh[n][1] = bb.y; hh[n][2] = bb.x; hh[n][3] = bb.y;
        }
#pragma unroll
        for (int n = 0; n < 4; n++) mma_bf16(hh[n], Aa0, wfrag[0 + n][lane]);
#pragma unroll
        for (int n = 0; n < 4; n++) mma_bf16(hh[n], Aa1, wfrag[4 + n][lane]);
        // relu -> layer 2 (ang_w2)
#pragma unroll
        for (int ss = 0; ss < 2; ss++) {
            A[0] = packbf(fmaxf(hh[2*ss][0], 0.f), fmaxf(hh[2*ss][1], 0.f));
            A[1] = packbf(fmaxf(hh[2*ss][2], 0.f), fmaxf(hh[2*ss][3], 0.f));
            A[2] = packbf(fmaxf(hh[2*ss+1][0], 0.f), fmaxf(hh[2*ss+1][1], 0.f));
            A[3] = packbf(fmaxf(hh[2*ss+1][2], 0.f), fmaxf(hh[2*ss+1][3], 0.f));
#pragma unroll
            for (int n = 0; n < 4; n++) mma_bf16(c2[n], A, wfrag[16 + ss * 4 + n][lane]);
        }

        // MLP(dists) layer 1
#pragma unroll
        for (int n = 0; n < 4; n++) {
            const float2 bb = bfr[1][n][lane];
            hh[n][0] = bb.x; hh[n][1] = bb.y; hh[n][2] = bb.x; hh[n][3] = bb.y;
        }
#pragma unroll
        for (int n = 0; n < 4; n++) mma_bf16(hh[n], Ad0, wfrag[8 + n][lane]);
#pragma unroll
        for (int n = 0; n < 4; n++) mma_bf16(hh[n], Ad1, wfrag[12 + n][lane]);
        // relu -> layer 2 (md_w2)
#pragma unroll
        for (int ss = 0; ss < 2; ss++) {
            A[0] = packbf(fmaxf(hh[2*ss][0], 0.f), fmaxf(hh[2*ss][1], 0.f));
            A[1] = packbf(fmaxf(hh[2*ss][2], 0.f), fmaxf(hh[2*ss][3], 0.f));
            A[2] = packbf(fmaxf(hh[2*ss+1][0], 0.f), fmaxf(hh[2*ss+1][1], 0.f));
            A[3] = packbf(fmaxf(hh[2*ss+1][2], 0.f), fmaxf(hh[2*ss+1][3], 0.f));
#pragma unroll
            for (int n = 0; n < 4; n++) mma_bf16(c2[n], A, wfrag[24 + ss * 4 + n][lane]);
        }

        // ---- fused edge contributions for this 16-j window ----
        if (ne) {
#pragma unroll
            for (int half = 0; half < 3; half++) {
                const int ereg = (half == 0) ? eb0 : (half == 1) ? eb1 : eb2;
                unsigned m = __ballot_sync(0xffffffffu,
                    ereg >= 0 && (unsigned)((ereg >> 13) - 1 - j0) < 16u);
                while (m) {
                    const int k = __ffs(m) - 1;
                    m &= m - 1;
                    const int ent = __shfl_sync(0xffffffffu, ereg, k);
                    const int rel = (ent >> 13) - 1 - j0;     // 0..15
                    const int e   = ent & (NE - 1);
                    const float2* vp = (const float2*)(g_vals + (size_t)(g * NE + e) * HH);
                    if (rel < 8) {
                        if (qid == rel) {
#pragma unroll
                            for (int n = 0; n < 4; n++) {
                                const float2 v = vp[n * 4 + tq];
                                c2[n][0] += v.x; c2[n][1] += v.y;
                            }
                        }
                    } else {
                        if (qid == rel - 8) {
#pragma unroll
                            for (int n = 0; n < 4; n++) {
                                const float2 v = vp[n * 4 + tq];
                                c2[n][2] += v.x; c2[n][3] += v.y;
                            }
                        }
                    }
                }
            }
        }

        // ---- add attn_bias base, store (streaming: write-once data) ----
#pragma unroll
        for (int n = 0; n < 4; n++) {
            float* o = outRow + (size_t)(n * 8 + tq * 2) * PLANE;
            __stcs(o + j0 + 1 + qid,         c2[n][0] + cat0);
            __stcs(o + PLANE + j0 + 1 + qid, c2[n][1] + cat0);
            __stcs(o + j0 + 9 + qid,         c2[n][2] + cat1);
            __stcs(o + PLANE + j0 + 9 + qid, c2[n][3] + cat1);
        }
    }

    // ---- fused col-0 (attn + virt) for this row; self-clean bucket count ----
    if (warp == 0) {
        const float a0 = attnRow[0];
        __stcs(outRow + (size_t)lane * PLANE, a0 + virt[lane]);
    }
    if (tid == 0) g_cnt[g * NP1 + i] = 0;
}

// ---------------------------------------------------------------------------
// Kernel B: row-0 fill: out[g,h,0,j] = attn[g,0,j] + virt[h]  (coalesced)
// ---------------------------------------------------------------------------
__global__ __launch_bounds__(256) void row0_kernel(
    const float* __restrict__ attn_bias,
    const float* __restrict__ virt,
    float* __restrict__ out)
{
    const int idx = blockIdx.x * 256 + threadIdx.x;
    const int total = NG * HH * NP1;
    if (idx >= total) return;
    const int j  = idx % NP1;
    const int gh = idx / NP1;
    const int h = gh & 31;
    const int g = gh >> 5;
    __stcs(out + ((size_t)(g * HH + h)) * PLANE + j,
           attn_bias[(size_t)g * PLANE + j] + virt[h]);
}

// ---------------------------------------------------------------------------
extern "C" void kernel_launch(void* const* d_in, const int* in_sizes, int n_in,
                              void* d_out, int out_size) {
    const float* edge_feat  = (const float*)d_in[0];
    const int*   edge_index = (const int*)d_in[1];
    const int*   edge_mask  = (const int*)d_in[2];
    const int*   num_lig    = (const int*)d_in[3];
    const float* attn_bias  = (const float*)d_in[4];
    const float* angle      = (const float*)d_in[5];
    const float* dists      = (const float*)d_in[6];
    // d_in[7] node_feat unused
    const float* struct_emb = (const float*)d_in[8];
    const float* plip_lig   = (const float*)d_in[9];
    const float* plip_prot  = (const float*)d_in[10];
    const float* plip_inter = (const float*)d_in[11];
    const float* dist_w1 = (const float*)d_in[12];
    const float* dist_b1 = (const float*)d_in[13];
    const float* dist_w2 = (const float*)d_in[14];
    const float* dist_b2 = (const float*)d_in[15];
    const float* ang_w1  = (const float*)d_in[16];
    const float* ang_b1  = (const float*)d_in[17];
    const float* ang_w2  = (const float*)d_in[18];
    const float* ang_b2  = (const float*)d_in[19];
    const float* md_w1   = (const float*)d_in[20];
    const float* md_b1   = (const float*)d_in[21];
    const float* md_w2   = (const float*)d_in[22];
    const float* md_b2   = (const float*)d_in[23];
    const float* virt    = (const float*)d_in[24];
    float* out = (float*)d_out;

    // efill (vals + buckets) -> interior (consumes + self-cleans + col0) -> row0
    efill_kernel<<<NG * NE / 128, 256>>>(edge_feat, edge_index, edge_mask, num_lig,
                                         struct_emb, plip_lig, plip_prot, plip_inter,
                                         dist_w1, dist_b1, dist_w2, dist_b2);
    interior_kernel<<<NG * NN, 256>>>(attn_bias, angle, dists,
                                      ang_w1, ang_b1, ang_w2, ang_b2,
                                      md_w1, md_b1, md_w2, md_b2, virt, out);
    row0_kernel<<<(NG * HH * NP1 + 255) / 256, 256>>>(attn_bias, virt, out);
}

// round 17
// speedup vs baseline: 1.3482x; 1.0370x over previous
#include <cuda_runtime.h>
#include <cuda_bf16.h>
#include <cstdint>

#define NG 8
#define NE 8192
#define NN 512
#define NP1 513
#define HH 32
#define PLANE (513*513)
#define CAP 96          // per-(g,row) edge bucket capacity (max expected ~38)
#define EGRID (NG * NE / 128)        // 512 efill blocks
#define R0GRID ((NG * HH * NP1 + 255) / 256)   // 513 row0 blocks

// ---------------------------------------------------------------------------
// scratch (static __device__ arrays; zero-initialized at module load).
// g_cnt is self-cleaning: interior zeros each entry after consuming it, so
// every execution (correctness run, each graph replay) starts from zeros.
// ---------------------------------------------------------------------------
__device__ float g_vals[NG * NE * HH];          // per-edge 32-head vector (8.4MB)
__device__ int   g_bucket[NG * NP1 * CAP];      // packed (e | col<<13)
__device__ int   g_cnt[NG * NP1];               // bucket counts

// ---------------------------------------------------------------------------
// helpers
// ---------------------------------------------------------------------------
__device__ __forceinline__ unsigned packbf(float lo, float hi) {
    __nv_bfloat162 t = __floats2bfloat162_rn(lo, hi);
    return *reinterpret_cast<unsigned*>(&t);
}
__device__ __forceinline__ unsigned packbf2(float2 v) { return packbf(v.x, v.y); }

__device__ __forceinline__ void mma_bf16(float* c, const unsigned* a, uint2 b) {
    asm volatile(
        "mma.sync.aligned.m16n8k16.row.col.f32.bf16.bf16.f32 "
        "{%0,%1,%2,%3}, {%4,%5,%6,%7}, {%8,%9}, {%0,%1,%2,%3};\n"
        : "+f"(c[0]), "+f"(c[1]), "+f"(c[2]), "+f"(c[3])
        : "r"(a[0]), "r"(a[1]), "r"(a[2]), "r"(a[3]), "r"(b.x), "r"(b.y));
}

__device__ __forceinline__ void ldm4(unsigned* r, uint32_t addr) {
    asm volatile("ldmatrix.sync.aligned.m8n8.x4.shared.b16 {%0,%1,%2,%3}, [%4];"
                 : "=r"(r[0]), "=r"(r[1]), "=r"(r[2]), "=r"(r[3]) : "r"(addr));
}

// ---------------------------------------------------------------------------
// efill (+row0): blocks < EGRID: per-edge MLP via 16x32x32 bf16 mma ->
// g_vals + bucket push. blocks >= EGRID: row-0 fill (disjoint out region,
// independent of everything else -> safe to overlap).
// ---------------------------------------------------------------------------
__global__ __launch_bounds__(256) void efill_kernel(
    const float* __restrict__ edge_feat,
    const int*   __restrict__ edge_index,
    const int*   __restrict__ edge_mask,
    const int*   __restrict__ num_ligand_atoms,
    const float* __restrict__ struct_emb,
    const float* __restrict__ plip_lig,
    const float* __restrict__ plip_prot,
    const float* __restrict__ plip_inter,
    const float* __restrict__ dist_w1, const float* __restrict__ dist_b1,
    const float* __restrict__ dist_w2, const float* __restrict__ dist_b2,
    const float* __restrict__ attn_bias,
    const float* __restrict__ virt,
    float* __restrict__ out)
{
    // ---- row0 part (whole block branches uniformly; no syncs crossed) ----
    if (blockIdx.x >= EGRID) {
        const int idx = (blockIdx.x - EGRID) * 256 + threadIdx.x;
        if (idx < NG * HH * NP1) {
            const int j  = idx % NP1;
            const int gh = idx / NP1;
            const int h = gh & 31;
            const int g = gh >> 5;
            __stcs(out + ((size_t)(g * HH + h)) * PLANE + j,
                   attn_bias[(size_t)g * PLANE + j] + virt[h]);
        }
        return;
    }

    __shared__ uint2 wf[2][4][32];           // layer-2 B-frags [kstep][n][lane]
    __shared__ float s_w1[32], s_b1[32], s_b2[32];

    const int tid = threadIdx.x;
    // build B fragments of dist_w2 (same builder as interior's wfrag)
    {
        const int p = tid >> 5, ln = tid & 31;
        const int s = p >> 2, n = p & 3;
        const int q = ln >> 2, t4 = ln & 3;
        const int r0 = s * 16 + t4 * 2;
        const int c  = n * 8 + q;
        wf[s][n][ln] = make_uint2(
            packbf(dist_w2[r0 * 32 + c],       dist_w2[(r0 + 1) * 32 + c]),
            packbf(dist_w2[(r0 + 8) * 32 + c], dist_w2[(r0 + 9) * 32 + c]));
    }
    if (tid < 32) {
        s_w1[tid] = dist_w1[tid];
        s_b1[tid] = dist_b1[tid];
        s_b2[tid] = dist_b2[tid];
    }
    __syncthreads();

    const int warp = tid >> 5;
    const int lane = tid & 31;
    const int qid  = lane >> 2;
    const int tq   = lane & 3;

    const int ebase = (blockIdx.x * 8 + warp) * 16;
    const int g = ebase >> 13;                         // same g for all 16 edges
    const int el0 = ebase & (NE - 1);                  // local edge base
    int nl = num_ligand_atoms[g];
    nl = nl > 1 ? nl : 1;

    // ---- lane-per-edge loads (lanes 0..15) ----
    int myact = 0, mysrc = 0, mytgt = 0;
    float myd = 0.f;
    const float* mysel = nullptr;
    if (lane < 16) {
        const int eid = ebase + lane;
        if (edge_mask[eid] != 0) {
            myact = 1;
            const int e = el0 + lane;
            const float4 ef = reinterpret_cast<const float4*>(edge_feat)[eid];
            const int t0 = (int)ef.x;
            const int t1 = (int)ef.y;
            const int t2 = (int)ef.z;
            myd = ef.w;
            mysrc = edge_index[(size_t)g * 2 * NE + e];
            mytgt = edge_index[(size_t)g * 2 * NE + NE + e];
            const bool sl = (mysrc > 0) && (mysrc < nl);
            const bool tl = (mytgt > 0) && (mytgt < nl);
            if (t0 <= 1) {
                int si = t0 * 4 + t1 * 2 + t2;
                si = si < 0 ? 0 : (si > 19 ? 19 : si);
                mysel = struct_emb + si * 32;
            } else if (t0 == 5) {
                int pi = t1 < 0 ? 0 : (t1 > 14 ? 14 : t1);
                const float* tab = (sl && tl) ? plip_lig
                                 : ((!sl && !tl) ? plip_prot : plip_inter);
                mysel = tab + pi * 32;
            }
        }
    }
    const unsigned full = 0xffffffffu;
    const unsigned amask = __ballot_sync(full, myact) & 0xffffu;
    if (!amask) return;                                  // whole tile masked

    const float d_lo = __shfl_sync(full, myd, qid);
    const float d_hi = __shfl_sync(full, myd, qid + 8);
    const float* plo = (const float*)__shfl_sync(full, (unsigned long long)mysel, qid);
    const float* phi = (const float*)__shfl_sync(full, (unsigned long long)mysel, qid + 8);

    // ---- C init: b2 + sel (fp32 exact) ----
    float c[4][4];
#pragma unroll
    for (int n = 0; n < 4; n++) {
        const int h0 = n * 8 + tq * 2;
        const float b0 = s_b2[h0], b1v = s_b2[h0 + 1];
        float2 vlo = plo ? *(const float2*)(plo + h0) : make_float2(0.f, 0.f);
        float2 vhi = phi ? *(const float2*)(phi + h0) : make_float2(0.f, 0.f);
        c[n][0] = b0 + vlo.x; c[n][1] = b1v + vlo.y;
        c[n][2] = b0 + vhi.x; c[n][3] = b1v + vhi.y;
    }

    // ---- layer 1 in A-frag layout + layer 2 mma ----
#pragma unroll
    for (int s = 0; s < 2; s++) {
        const int m0 = s * 16 + tq * 2;
        const int m2 = m0 + 8;
        unsigned A[4];
        A[0] = packbf(fmaxf(fmaf(d_lo, s_w1[m0], s_b1[m0]), 0.f),
                      fmaxf(fmaf(d_lo, s_w1[m0 + 1], s_b1[m0 + 1]), 0.f));
        A[1] = packbf(fmaxf(fmaf(d_hi, s_w1[m0], s_b1[m0]), 0.f),
                      fmaxf(fmaf(d_hi, s_w1[m0 + 1], s_b1[m0 + 1]), 0.f));
        A[2] = packbf(fmaxf(fmaf(d_lo, s_w1[m2], s_b1[m2]), 0.f),
                      fmaxf(fmaf(d_lo, s_w1[m2 + 1], s_b1[m2 + 1]), 0.f));
        A[3] = packbf(fmaxf(fmaf(d_hi, s_w1[m2], s_b1[m2]), 0.f),
                      fmaxf(fmaf(d_hi, s_w1[m2 + 1], s_b1[m2 + 1]), 0.f));
#pragma unroll
        for (int n = 0; n < 4; n++) mma_bf16(c[n], A, wf[s][n][lane]);
    }

    // ---- stores (mirror of interior's fused-edge read pattern) ----
    const int act_lo = (amask >> qid) & 1;
    const int act_hi = (amask >> (qid + 8)) & 1;
#pragma unroll
    for (int n = 0; n < 4; n++) {
        const int h0 = n * 8 + tq * 2;
        if (act_lo)
            *(float2*)&g_vals[(size_t)(ebase + qid) * HH + h0] =
                make_float2(c[n][0], c[n][1]);
        if (act_hi)
            *(float2*)&g_vals[(size_t)(ebase + qid + 8) * HH + h0] =
                make_float2(c[n][2], c[n][3]);
    }

    // ---- bucket pushes (lane-per-edge) ----
    if (lane < 16 && myact) {
        const int row = mysrc + 1;                 // 1..512
        const int slot = atomicAdd(&g_cnt[g * NP1 + row], 1);
        if (slot < CAP)
            g_bucket[(g * NP1 + row) * CAP + slot] = (el0 + lane) | ((mytgt + 1) << 13);
    }
}

// ---------------------------------------------------------------------------
// Kernel A: interior fill  out[g,h,i,j] for i,j in [1,512]
// + fused edge contributions + col-0 (attn + virt) + self-cleaning g_cnt.
// Bias-in-padding: layer-1 b1 lives in wfrag row 28, A col 28 = 1.0 ->
// hh init is zero and bfr[0]/bfr[1] LDS per tile are eliminated.
// ---------------------------------------------------------------------------
__global__ __launch_bounds__(256, 2) void interior_kernel(
    const float* __restrict__ attn_bias,
    const float* __restrict__ angle,
    const float* __restrict__ dists,
    const float* __restrict__ ang_w1, const float* __restrict__ ang_b1,
    const float* __restrict__ ang_w2, const float* __restrict__ ang_b2,
    const float* __restrict__ md_w1,  const float* __restrict__ md_b1,
    const float* __restrict__ md_w2,  const float* __restrict__ md_b2,
    const float* __restrict__ virt,
    float* __restrict__ out)
{
    __shared__ uint2  wfrag[32][32];                       // [m*8+s*4+n][lane]
    __shared__ float2 bfr2[4][32];                         // b2 sums [n][lane]
    __shared__ __align__(128) unsigned char mbuf[8][2560]; // per-warp ldmatrix buf

    const int tid = threadIdx.x;

    for (int e = tid; e < 1024; e += 256) {
        const int p = e >> 5, ln = e & 31;
        const int m = p >> 3, s = (p >> 2) & 1, n = p & 3;
        const int q = ln >> 2, tq4 = ln & 3;
        const int r0 = s * 16 + tq4 * 2;
        const int c  = n * 8 + q;
        const float* w = (m == 0) ? ang_w1 : (m == 1) ? md_w1 : (m == 2) ? ang_w2 : md_w2;
        const bool pad = (m < 2);   // w1 matrices: rows 28..31 padded
        const float* b1 = (m == 0) ? ang_b1 : md_b1;
        // r0, r0+1 <= 23: never padded. r0+8 can be 28 (bias row), r0+9 odd.
        float v00 = w[r0 * 32 + c];
        float v01 = w[(r0 + 1) * 32 + c];
        float v10, v11;
        if (pad && r0 + 8 >= 28) {
            v10 = (r0 + 8 == 28) ? b1[c] : 0.f;    // row 28 carries b1
            v11 = 0.f;
        } else {
            v10 = w[(r0 + 8) * 32 + c];
            v11 = w[(r0 + 9) * 32 + c];
        }
        wfrag[p][ln] = make_uint2(packbf(v00, v01), packbf(v10, v11));
    }
    for (int e = tid; e < 128; e += 256) {
        const int n = e >> 5, ln = e & 31;
        const int i2 = n * 8 + (ln & 3) * 2;
        bfr2[n][ln] = make_float2(ang_b2[i2] + md_b2[i2],
                                  ang_b2[i2 + 1] + md_b2[i2 + 1]);
    }
    // pad cols 28..31 of every staged row: col 28 = 1.0 (bias multiplier),
    // cols 29-31 = 0. Converter only writes cols 0..27, so this persists.
    *(unsigned*)(mbuf[tid >> 5] + (tid & 31) * 80 + 56) = packbf(1.0f, 0.f);
    *(unsigned*)(mbuf[tid >> 5] + (tid & 31) * 80 + 60) = 0u;
    __syncthreads();

    const int lane = tid & 31;
    const int warp = tid >> 5;
    const int qid  = lane >> 2;
    const int tq   = lane & 3;

    const int bid = blockIdx.x;
    const int g = bid >> 9;
    const int i = (bid & 511) + 1;
    const size_t rowp = (size_t)(g * NN + (i - 1)) * NN * 28;
    const float* angRow  = angle + rowp;
    const float* dstRow  = dists + rowp;
    const float* attnRow = attn_bias + ((size_t)g * NP1 + i) * NP1;
    float* outRow = out + (size_t)g * HH * PLANE + (size_t)i * NP1;

    // ---- edge bucket for this row (warp-resident) ----
    const int ne = min(g_cnt[g * NP1 + i], CAP);
    const int bbase = (g * NP1 + i) * CAP;
    int eb0 = (lane      < ne) ? g_bucket[bbase + lane]      : -1;
    int eb1 = (lane + 32 < ne) ? g_bucket[bbase + lane + 32] : -1;
    int eb2 = (lane + 64 < ne) ? g_bucket[bbase + lane + 64] : -1;

    const uint32_t abase = (uint32_t)__cvta_generic_to_shared(mbuf[warp]);
    const uint32_t dbase = abase + 1280;
    const uint32_t lm_off = (uint32_t)((lane & 15) * 80 + ((lane >> 4) << 4));

    float2 ra[7], rd[7];
    float at0, at1;
    {
        const float2* a2 = (const float2*)angRow + (size_t)(warp * 16) * 14;
        const float2* d2 = (const float2*)dstRow + (size_t)(warp * 16) * 14;
#pragma unroll
        for (int k = 0; k < 7; k++) {
            ra[k] = __ldcs(a2 + lane + 32 * k);
            rd[k] = __ldcs(d2 + lane + 32 * k);
        }
        at0 = __ldg(attnRow + warp * 16 + 1 + qid);
        at1 = __ldg(attnRow + warp * 16 + 9 + qid);
    }

#pragma unroll
    for (int it = 0; it < 4; it++) {
        const int t  = warp + it * 8;
        const int j0 = t * 16;

        __syncwarp();
#pragma unroll
        for (int k = 0; k < 7; k++) {
            const int f   = lane + 32 * k;
            const int row = f / 14;
            const int c   = f - row * 14;
            const int off = row * 80 + c * 4;
            *(unsigned*)(mbuf[warp] + off)        = packbf2(ra[k]);
            *(unsigned*)(mbuf[warp] + 1280 + off) = packbf2(rd[k]);
        }
        __syncwarp();

        unsigned Aa0[4], Aa1[4], Ad0[4], Ad1[4];
        ldm4(Aa0, abase + lm_off);
        ldm4(Aa1, abase + lm_off + 32);
        ldm4(Ad0, dbase + lm_off);
        ldm4(Ad1, dbase + lm_off + 32);

        const float cat0 = at0, cat1 = at1;

        if (it < 3) {
            const int jn = (t + 8) * 16;
            const float2* a2 = (const float2*)angRow + (size_t)jn * 14;
            const float2* d2 = (const float2*)dstRow + (size_t)jn * 14;
#pragma unroll
            for (int k = 0; k < 7; k++) {
                ra[k] = __ldcs(a2 + lane + 32 * k);
                rd[k] = __ldcs(d2 + lane + 32 * k);
            }
            at0 = __ldg(attnRow + jn + 1 + qid);
            at1 = __ldg(attnRow + jn + 9 + qid);
        }

        float c2[4][4];
#pragma unroll
        for (int n = 0; n < 4; n++) {
            const float2 bb = bfr2[n][lane];
            c2[n][0] = bb.x; c2[n][1] = bb.y; c2[n][2] = bb.x; c2[n][3] = bb.y;
        }

        float hh[4][4];
        unsigned A[4];

        // MLP(angle) layer 1 (bias arrives via pad row 28 x A col 28 = 1.0)
#pragma unroll
        for (int n = 0; n < 4; n++) {
            hh[n][0] = 0.f; hh[n][1] = 0.f; hh[n][2] = 0.f; hh[n][3] = 0.f;
        }
#pragma unroll
        for (int n = 0; n < 4; n++) mma_bf16(hh[n], Aa0, wfrag[0 + n][lane]);
#pragma unroll
        for (int n = 0; n < 4; n++) mma_bf16(hh[n], Aa1, wfrag[4 + n][lane]);
        // relu -> layer 2 (ang_w2)
#pragma unroll
        for (int ss = 0; ss < 2; ss++) {
            A[0] = packbf(fmaxf(hh[2*ss][0], 0.f), fmaxf(hh[2*ss][1], 0.f));
            A[1] = packbf(fmaxf(hh[2*ss][2], 0.f), fmaxf(hh[2*ss][3], 0.f));
            A[2] = packbf(fmaxf(hh[2*ss+1][0], 0.f), fmaxf(hh[2*ss+1][1], 0.f));
            A[3] = packbf(fmaxf(hh[2*ss+1][2], 0.f), fmaxf(hh[2*ss+1][3], 0.f));
#pragma unroll
            for (int n = 0; n < 4; n++) mma_bf16(c2[n], A, wfrag[16 + ss * 4 + n][lane]);
        }

        // MLP(dists) layer 1
#pragma unroll
        for (int n = 0; n < 4; n++) {
            hh[n][0] = 0.f; hh[n][1] = 0.f; hh[n][2] = 0.f; hh[n][3] = 0.f;
        }
#pragma unroll
        for (int n = 0; n < 4; n++) mma_bf16(hh[n], Ad0, wfrag[8 + n][lane]);
#pragma unroll
        for (int n = 0; n < 4; n++) mma_bf16(hh[n], Ad1, wfrag[12 + n][lane]);
        // relu -> layer 2 (md_w2)
#pragma unroll
        for (int ss = 0; ss < 2; ss++) {
            A[0] = packbf(fmaxf(hh[2*ss][0], 0.f), fmaxf(hh[2*ss][1], 0.f));
            A[1] = packbf(fmaxf(hh[2*ss][2], 0.f), fmaxf(hh[2*ss][3], 0.f));
            A[2] = packbf(fmaxf(hh[2*ss+1][0], 0.f), fmaxf(hh[2*ss+1][1], 0.f));
            A[3] = packbf(fmaxf(hh[2*ss+1][2], 0.f), fmaxf(hh[2*ss+1][3], 0.f));
#pragma unroll
            for (int n = 0; n < 4; n++) mma_bf16(c2[n], A, wfrag[24 + ss * 4 + n][lane]);
        }

        // ---- fused edge contributions for this 16-j window ----
        if (ne) {
#pragma unroll
            for (int half = 0; half < 3; half++) {
                const int ereg = (half == 0) ? eb0 : (half == 1) ? eb1 : eb2;
                unsigned m = __ballot_sync(0xffffffffu,
                    ereg >= 0 && (unsigned)((ereg >> 13) - 1 - j0) < 16u);
                while (m) {
                    const int k = __ffs(m) - 1;
                    m &= m - 1;
                    const int ent = __shfl_sync(0xffffffffu, ereg, k);
                    const int rel = (ent >> 13) - 1 - j0;     // 0..15
                    const int e   = ent & (NE - 1);
                    const float2* vp = (const float2*)(g_vals + (size_t)(g * NE + e) * HH);
                    if (rel < 8) {
                        if (qid == rel) {
#pragma unroll
                            for (int n = 0; n < 4; n++) {
                                const float2 v = vp[n * 4 + tq];
                                c2[n][0] += v.x; c2[n][1] += v.y;
                            }
                        }
                    } else {
                        if (qid == rel - 8) {
#pragma unroll
                            for (int n = 0; n < 4; n++) {
                                const float2 v = vp[n * 4 + tq];
                                c2[n][2] += v.x; c2[n][3] += v.y;
                            }
                        }
                    }
                }
            }
        }

        // ---- add attn_bias base, store (streaming: write-once data) ----
#pragma unroll
        for (int n = 0; n < 4; n++) {
            float* o = outRow + (size_t)(n * 8 + tq * 2) * PLANE;
            __stcs(o + j0 + 1 + qid,         c2[n][0] + cat0);
            __stcs(o + PLANE + j0 + 1 + qid, c2[n][1] + cat0);
            __stcs(o + j0 + 9 + qid,         c2[n][2] + cat1);
            __stcs(o + PLANE + j0 + 9 + qid, c2[n][3] + cat1);
        }
    }

    // ---- fused col-0 (attn + virt) for this row; self-clean bucket count ----
    if (warp == 0) {
        const float a0 = attnRow[0];
        __stcs(outRow + (size_t)lane * PLANE, a0 + virt[lane]);
    }
    if (tid == 0) g_cnt[g * NP1 + i] = 0;
}

// ---------------------------------------------------------------------------
extern "C" void kernel_launch(void* const* d_in, const int* in_sizes, int n_in,
                              void* d_out, int out_size) {
    const float* edge_feat  = (const float*)d_in[0];
    const int*   edge_index = (const int*)d_in[1];
    const int*   edge_mask  = (const int*)d_in[2];
    const int*   num_lig    = (const int*)d_in[3];
    const float* attn_bias  = (const float*)d_in[4];
    const float* angle      = (const float*)d_in[5];
    const float* dists      = (const float*)d_in[6];
    // d_in[7] node_feat unused
    const float* struct_emb = (const float*)d_in[8];
    const float* plip_lig   = (const float*)d_in[9];
    const float* plip_prot  = (const float*)d_in[10];
    const float* plip_inter = (const float*)d_in[11];
    const float* dist_w1 = (const float*)d_in[12];
    const float* dist_b1 = (const float*)d_in[13];
    const float* dist_w2 = (const float*)d_in[14];
    const float* dist_b2 = (const float*)d_in[15];
    const float* ang_w1  = (const float*)d_in[16];
    const float* ang_b1  = (const float*)d_in[17];
    const float* ang_w2  = (const float*)d_in[18];
    const float* ang_b2  = (const float*)d_in[19];
    const float* md_w1   = (const float*)d_in[20];
    const float* md_b1   = (const float*)d_in[21];
    const float* md_w2   = (const float*)d_in[22];
    const float* md_b2   = (const float*)d_in[23];
    const float* virt    = (const float*)d_in[24];
    float* out = (float*)d_out;

    // efill+row0 (vals + buckets + row0 fill) -> interior (consumes + col0)
    efill_kernel<<<EGRID + R0GRID, 256>>>(edge_feat, edge_index, edge_mask, num_lig,
                                          struct_emb, plip_lig, plip_prot, plip_inter,
                                          dist_w1, dist_b1, dist_w2, dist_b2,
                                          attn_bias, virt, out);
    interior_kernel<<<NG * NN, 256>>>(attn_bias, angle, dists,
                                      ang_w1, ang_b1, ang_w2, ang_b2,
                                      md_w1, md_b1, md_w2, md_b2, virt, out);
}